// round 12
// baseline (speedup 1.0000x reference)
#include <cuda_runtime.h>
#include <cuda_bf16.h>
#include <math.h>
#include <stdint.h>

// ---------------- problem constants ----------------
#define IN_DIM   36
#define NORM_EPS 1e-5f
#define L2E      1.4426950408889634f

// folded fp32 params from prep_kernel
#define P_W1   0        // 152*36 : (in_proj @ f_out_w), conv scale folded into rows 64..143
#define P_WOUT 5472     // 64*32  : [d][o] = out_proj[o][d]*norm_w[d]
#define P_B1   7520     // 152    : fully folded biases
#define P_DSK  7840     // 8
#define P_TOTAL 7848

__device__ float g_params[P_TOTAL];

// k16 fragment table: W1 recs idx = nt*4 + kk*2 + m  (nt<19, kk<2)  -> 76
//                     W2 recs idx = 76 + nt*8 + kk*2 + m (nt<4,kk<4) -> 32
#define NREC16 108
// fused-tail table (one uint2 rec per W1 n-tile, carries bias in k12/k13): 19
#define NTAIL  19

// ---------------- helpers ----------------
__device__ __forceinline__ uint32_t pk2(float a, float b) {   // lo=a, hi=b
    uint32_t r;
    asm("cvt.rn.bf16x2.f32 %0, %1, %2;" : "=r"(r) : "f"(b), "f"(a));
    return r;
}
__device__ __forceinline__ float lo16f(uint32_t p) { return __uint_as_float(p << 16); }
__device__ __forceinline__ float hi16f(uint32_t p) { return __uint_as_float(p & 0xffff0000u); }

__device__ __forceinline__ void mma16(float* c, const uint32_t* a,
                                      uint32_t b0, uint32_t b1) {
    asm volatile(
        "mma.sync.aligned.m16n8k16.row.col.f32.bf16.bf16.f32 "
        "{%0,%1,%2,%3}, {%4,%5,%6,%7}, {%8,%9}, {%0,%1,%2,%3};"
        : "+f"(c[0]), "+f"(c[1]), "+f"(c[2]), "+f"(c[3])
        : "r"(a[0]), "r"(a[1]), "r"(a[2]), "r"(a[3]), "r"(b0), "r"(b1));
}
// first MMA of an accumulator: D = A*B + 0 (no init movs; C = zeros -> RZ)
__device__ __forceinline__ void mma16_init(float* c, const uint32_t* a,
                                           uint32_t b0, uint32_t b1) {
    asm volatile(
        "mma.sync.aligned.m16n8k16.row.col.f32.bf16.bf16.f32 "
        "{%0,%1,%2,%3}, {%4,%5,%6,%7}, {%8,%9}, {%10,%10,%10,%10};"
        : "=f"(c[0]), "=f"(c[1]), "=f"(c[2]), "=f"(c[3])
        : "r"(a[0]), "r"(a[1]), "r"(a[2]), "r"(a[3]), "r"(b0), "r"(b1),
          "f"(0.0f));
}

__device__ __forceinline__ float rcpf(float v) {
    float r; asm("rcp.approx.f32 %0, %1;" : "=f"(r) : "f"(v)); return r;
}
__device__ __forceinline__ float ex2f(float v) {
    float r; asm("ex2.approx.f32 %0, %1;" : "=f"(r) : "f"(v)); return r;
}
// denominator of silu(a)*silu(b): (1+e^-a)(1+e^-b)
__device__ __forceinline__ float silu_den(float a, float b) {
    return (1.0f + __expf(-a)) * (1.0f + __expf(-b));
}
__device__ __forceinline__ float softplus1(float v) {
    return fmaxf(v, 0.0f) + __logf(1.0f + __expf(-fabsf(v)));
}

// ---------------- prep: fold weights on device ----------------
__global__ void prep_kernel(const float* __restrict__ f_out_w,
                            const float* __restrict__ f_out_b,
                            const float* __restrict__ in_proj_w,
                            const float* __restrict__ conv_w,
                            const float* __restrict__ conv_b,
                            const float* __restrict__ dt_bias,
                            const float* __restrict__ D_skip,
                            const float* __restrict__ norm_w,
                            const float* __restrict__ out_proj_w)
{
    int t = blockIdx.x * blockDim.x + threadIdx.x;
    int stride = gridDim.x * blockDim.x;
    // W1 rows: 0..63 z | 64..127 x | 128..135 B | 136..143 C | 144..151 dt
    for (int i = t; i < 152 * 36; i += stride) {
        int j = i / 36, k = i % 36;
        float s = 0.0f;
        #pragma unroll
        for (int m = 0; m < 32; m++) s += in_proj_w[j * 32 + m] * f_out_w[m * 36 + k];
        float scale = (j >= 64 && j < 144) ? conv_w[(j - 64) * 2 + 1] : 1.0f;
        g_params[P_W1 + i] = s * scale;
    }
    for (int i = t; i < 64 * 32; i += stride) {
        int d = i / 32, o = i % 32;
        g_params[P_WOUT + i] = out_proj_w[o * 64 + d] * norm_w[d];
    }
    for (int i = t; i < 152; i += stride) {
        float s = 0.0f;
        #pragma unroll
        for (int m = 0; m < 32; m++) s += in_proj_w[i * 32 + m] * f_out_b[m];
        float b;
        if (i < 64)       b = s;
        else if (i < 144) b = s * conv_w[(i - 64) * 2 + 1] + conv_b[i - 64];
        else              b = s + dt_bias[i - 144];
        g_params[P_B1 + i] = b;
    }
    for (int i = t; i < 8; i += stride) g_params[P_DSK + i] = D_skip[i];
}

// ---------------- main kernel: warp-MMA, 32 rows/warp (2 row-blocks) ----
__global__ __launch_bounds__(256, 2)
void mamba_hmma_kernel(const float* __restrict__ x,
                       float* __restrict__ out, int N)
{
    __shared__ uint2    s_frag [NREC16 * 32];   // 27.6 KB
    __shared__ uint2    s_ftail[NTAIL  * 32];   // 4.75 KB (fused tail + bias)
    __shared__ float    s_dsk[8];
    __shared__ float    s_coef[8][32][8];       // [warp][row][head]  8 KB

    const int tid  = threadIdx.x;
    const int lane = tid & 31;
    const int q    = lane & 3;
    const int g    = lane >> 2;
    const int w    = tid >> 5;

    // ---- build k16 fragment table ----
    for (int idx = tid; idx < NREC16 * 32; idx += 256) {
        int rec = idx >> 5, ln = idx & 31;
        int lq = ln & 3, lg = ln >> 2;
        float v0, v1, v2, v3;
        int m;
        if (rec < 76) {
            int nt = rec >> 2, rem = rec & 3;
            int kk = rem >> 1; m = rem & 1;
            int ch = nt * 8 + lg;
            int k0 = kk * 16 + 2 * lq;
            const float* wr = g_params + P_W1 + ch * 36;
            v0 = wr[k0]; v1 = wr[k0 + 1]; v2 = wr[k0 + 8]; v3 = wr[k0 + 9];
        } else {
            int r2 = rec - 76;
            int nt = r2 >> 3, rem = r2 & 7;
            int kk = rem >> 1; m = rem & 1;
            int o = nt * 8 + lg;
            int k0 = kk * 16 + 2 * lq;
            const float* w2 = g_params + P_WOUT;
            v0 = w2[(k0    ) * 32 + o];
            v1 = w2[(k0 + 1) * 32 + o];
            v2 = w2[(k0 + 8) * 32 + o];
            v3 = w2[(k0 + 9) * 32 + o];
        }
        uint32_t h01 = pk2(v0, v1), h23 = pk2(v2, v3);
        uint32_t r0, r1;
        if (m == 0) { r0 = h01; r1 = h23; }
        else {
            r0 = pk2(v0 - lo16f(h01), v1 - hi16f(h01));
            r1 = pk2(v2 - lo16f(h23), v3 - hi16f(h23));
        }
        s_frag[idx] = make_uint2(r0, r1);
    }
    // ---- fused-tail table ----
    for (int idx = tid; idx < NTAIL * 32; idx += 256) {
        int nt = idx >> 5, ln = idx & 31;
        int lq = ln & 3, lg = ln >> 2;
        const float* wr = g_params + P_W1 + (nt * 8 + lg) * 36;
        int i = (lq & 1) * 2;
        float v0 = wr[32 + i], v1 = wr[33 + i];
        uint32_t h = pk2(v0, v1);
        uint32_t l = pk2(v0 - lo16f(h), v1 - hi16f(h));
        float b = g_params[P_B1 + nt * 8 + lg];
        uint32_t bh = pk2(b, 0.f);
        uint32_t bias = pk2(lo16f(bh), b - lo16f(bh));   // (bh, bl)
        uint32_t b0 = (lq < 2) ? h : l;
        uint32_t b1 = (lq < 2) ? h : ((lq == 2) ? bias : 0u);
        s_ftail[idx] = make_uint2(b0, b1);
    }
    if (tid < 8) s_dsk[tid] = g_params[P_DSK + tid];
    __syncthreads();

    const int warp_global = blockIdx.x * 8 + w;
    const int nwarps = gridDim.x * 8;
    const int nchunks = (N + 31) >> 5;            // 32 rows per chunk
    const uint32_t ones2 = pk2(1.0f, 1.0f);

    for (int chk = warp_global; chk < nchunks; chk += nwarps) {
        const int base = chk << 5;
        const int r0 = base + g;                  // block0 rows: r0, r0+8
        const int r2 = base + 16 + g;             // block1 rows: r2, r2+8
        const bool p0 = r0 < N,      p1 = r0 + 8 < N;
        const bool p2 = r2 < N,      p3 = r2 + 8 < N;

        // ---- A1 fragments for both row-blocks ----
        uint32_t ah0[8], al0[8], at0[4];
        uint32_t ah1[8], al1[8], at1[4];
        #define BUILD_AFRAG(ah, al, at, ra, rb, pa, pb) do {                   \
            const float* rpa = x + (size_t)(ra) * IN_DIM;                      \
            const float* rpb = x + (size_t)(rb) * IN_DIM;                      \
            _Pragma("unroll")                                                  \
            for (int kk = 0; kk < 2; kk++) {                                   \
                int c  = kk * 16 + 2 * q;                                      \
                int c2 = c + 8;                                                \
                float2 xa0 = (pa) ? *(const float2*)(rpa + c)  : make_float2(0.f, 0.f); \
                float2 xb0 = (pb) ? *(const float2*)(rpb + c)  : make_float2(0.f, 0.f); \
                float2 xa2 = (pa) ? *(const float2*)(rpa + c2) : make_float2(0.f, 0.f); \
                float2 xb2 = (pb) ? *(const float2*)(rpb + c2) : make_float2(0.f, 0.f); \
                uint32_t h;                                                    \
                h = pk2(xa0.x, xa0.y); ah[kk*4+0] = h;                         \
                al[kk*4+0] = pk2(xa0.x - lo16f(h), xa0.y - hi16f(h));          \
                h = pk2(xb0.x, xb0.y); ah[kk*4+1] = h;                         \
                al[kk*4+1] = pk2(xb0.x - lo16f(h), xb0.y - hi16f(h));          \
                h = pk2(xa2.x, xa2.y); ah[kk*4+2] = h;                         \
                al[kk*4+2] = pk2(xa2.x - lo16f(h), xa2.y - hi16f(h));          \
                h = pk2(xb2.x, xb2.y); ah[kk*4+3] = h;                         \
                al[kk*4+3] = pk2(xb2.x - lo16f(h), xb2.y - hi16f(h));          \
            }                                                                  \
            {                                                                  \
                int c = 32 + ((q & 1) << 1);                                   \
                float2 xa = (pa) ? *(const float2*)(rpa + c) : make_float2(0.f, 0.f); \
                float2 xb = (pb) ? *(const float2*)(rpb + c) : make_float2(0.f, 0.f); \
                uint32_t h0 = pk2(xa.x, xa.y);                                 \
                uint32_t h1 = pk2(xb.x, xb.y);                                 \
                at[0] = h0;                                                    \
                at[1] = h1;                                                    \
                uint32_t l0 = pk2(xa.x - lo16f(h0), xa.y - hi16f(h0));         \
                uint32_t l1 = pk2(xb.x - lo16f(h1), xb.y - hi16f(h1));         \
                at[2] = (q < 2) ? l0 : ((q == 2) ? ones2 : 0u);                \
                at[3] = (q < 2) ? l1 : ((q == 2) ? ones2 : 0u);                \
            }                                                                  \
        } while (0)
        BUILD_AFRAG(ah0, al0, at0, r0, r0 + 8, p0, p1);
        BUILD_AFRAG(ah1, al1, at1, r2, r2 + 8, p2, p3);
        #undef BUILD_AFRAG

        // GEMM1 for one n-tile, BOTH blocks: shared fragment loads
        #define GEMM1_NT2(nt, c0, c1) do {                                    \
            {                                                                  \
                uint2 fh = s_frag[((nt) * 4 + 0) * 32 + lane];                 \
                uint2 fl = s_frag[((nt) * 4 + 1) * 32 + lane];                 \
                mma16_init(c0, ah0, fh.x, fh.y);                               \
                mma16(c0, ah0, fl.x, fl.y);                                    \
                mma16(c0, al0, fh.x, fh.y);                                    \
                mma16_init(c1, ah1, fh.x, fh.y);                               \
                mma16(c1, ah1, fl.x, fl.y);                                    \
                mma16(c1, al1, fh.x, fh.y);                                    \
            }                                                                  \
            {                                                                  \
                uint2 fh = s_frag[((nt) * 4 + 2) * 32 + lane];                 \
                uint2 fl = s_frag[((nt) * 4 + 3) * 32 + lane];                 \
                mma16(c0, ah0 + 4, fh.x, fh.y);                                \
                mma16(c0, ah0 + 4, fl.x, fl.y);                                \
                mma16(c0, al0 + 4, fh.x, fh.y);                                \
                mma16(c1, ah1 + 4, fh.x, fh.y);                                \
                mma16(c1, ah1 + 4, fl.x, fl.y);                                \
                mma16(c1, al1 + 4, fh.x, fh.y);                                \
            }                                                                  \
            {                                                                  \
                uint2 ft = s_ftail[(nt) * 32 + lane];                          \
                mma16(c0, at0, ft.x, ft.y);                                    \
                mma16(c1, at1, ft.x, ft.y);                                    \
            }                                                                  \
        } while (0)

        // ---- phase A: B, C, dt for both blocks ----
        {
            float cB0[4], cC0[4], cD0[4], cB1[4], cC1[4], cD1[4];
            GEMM1_NT2(16, cB0, cB1);
            GEMM1_NT2(17, cC0, cC1);
            GEMM1_NT2(18, cD0, cD1);
            float dsk0 = s_dsk[2 * q], dsk1 = s_dsk[2 * q + 1];
            #define PHASE_A(cB, cC, cD, rowa, rowb) do {                       \
                float n0 = cB[0] * cC[0], n1 = cB[1] * cC[1];                  \
                float n2 = cB[2] * cC[2], n3 = cB[3] * cC[3];                  \
                float d0 = silu_den(cB[0], cC[0]);                             \
                float d1 = silu_den(cB[1], cC[1]);                             \
                float d2 = silu_den(cB[2], cC[2]);                             \
                float d3 = silu_den(cB[3], cC[3]);                             \
                float p01 = d0 * d1, p23 = d2 * d3;                            \
                float r = rcpf(p01 * p23);                                     \
                float r01 = r * p23, r23 = r * p01;                            \
                float pra = n0 * (d1 * r01) + n1 * (d0 * r01);                 \
                float prb = n2 * (d3 * r23) + n3 * (d2 * r23);                 \
                pra += __shfl_xor_sync(0xffffffffu, pra, 1);                   \
                pra += __shfl_xor_sync(0xffffffffu, pra, 2);                   \
                prb += __shfl_xor_sync(0xffffffffu, prb, 1);                   \
                prb += __shfl_xor_sync(0xffffffffu, prb, 2);                   \
                float k00 = softplus1(cD[0]) * pra + dsk0;                     \
                float k01 = softplus1(cD[1]) * pra + dsk1;                     \
                float k10 = softplus1(cD[2]) * prb + dsk0;                     \
                float k11 = softplus1(cD[3]) * prb + dsk1;                     \
                *(float2*)&s_coef[w][rowa][2 * q] = make_float2(k00, k01);     \
                *(float2*)&s_coef[w][rowb][2 * q] = make_float2(k10, k11);     \
            } while (0)
            __syncwarp();
            PHASE_A(cB0, cC0, cD0, g,      g + 8);
            PHASE_A(cB1, cC1, cD1, g + 16, g + 24);
            __syncwarp();
            #undef PHASE_A
        }

        // ---- phase B: z/x -> gated y -> GEMM2, both blocks ----
        float co0[16], co1[16];
        float ssA0 = 0.f, ssA1 = 0.f, ssB0 = 0.f, ssB1 = 0.f;

        #pragma unroll
        for (int t = 0; t < 4; t++) {
            uint32_t a2h0[4], a2l0[4], a2h1[4], a2l1[4];
            #pragma unroll
            for (int u = 0; u < 2; u++) {
                const int j = 2 * t + u;
                float cz0[4], cx0[4], cz1[4], cx1[4];
                GEMM1_NT2(j, cz0, cz1);
                GEMM1_NT2(8 + j, cx0, cx1);
                #define GATE(cx, cz, rowa, rowb, ssa, ssb, a2h, a2l) do {      \
                    float cfa = s_coef[w][rowa][j];                            \
                    float cfb = s_coef[w][rowb][j];                            \
                    float n0 = cx[0] * cz[0] * cfa, n1 = cx[1] * cz[1] * cfa;  \
                    float n2 = cx[2] * cz[2] * cfb, n3 = cx[3] * cz[3] * cfb;  \
                    float d0 = silu_den(cx[0], cz[0]);                         \
                    float d1 = silu_den(cx[1], cz[1]);                         \
                    float d2 = silu_den(cx[2], cz[2]);                         \
                    float d3 = silu_den(cx[3], cz[3]);                         \
                    float p01 = d0 * d1, p23 = d2 * d3;                        \
                    float r = rcpf(p01 * p23);                                 \
                    float r01 = r * p23, r23 = r * p01;                        \
                    float y00 = n0 * (d1 * r01);                               \
                    float y01 = n1 * (d0 * r01);                               \
                    float y10 = n2 * (d3 * r23);                               \
                    float y11 = n3 * (d2 * r23);                               \
                    ssa += y00 * y00 + y01 * y01;                              \
                    ssb += y10 * y10 + y11 * y11;                              \
                    uint32_t h0 = pk2(y00, y01), h1 = pk2(y10, y11);           \
                    a2h[2*u]     = h0;                                         \
                    a2h[2*u + 1] = h1;                                         \
                    a2l[2*u]     = pk2(y00 - lo16f(h0), y01 - hi16f(h0));      \
                    a2l[2*u + 1] = pk2(y10 - lo16f(h1), y11 - hi16f(h1));      \
                } while (0)
                GATE(cx0, cz0, g,      g + 8,  ssA0, ssA1, a2h0, a2l0);
                GATE(cx1, cz1, g + 16, g + 24, ssB0, ssB1, a2h1, a2l1);
                #undef GATE
            }
            #pragma unroll
            for (int nt = 0; nt < 4; nt++) {
                uint2 fh = s_frag[(76 + nt * 8 + t * 2 + 0) * 32 + lane];
                uint2 fl = s_frag[(76 + nt * 8 + t * 2 + 1) * 32 + lane];
                if (t == 0) {
                    mma16_init(co0 + nt * 4, a2h0, fh.x, fh.y);
                    mma16_init(co1 + nt * 4, a2h1, fh.x, fh.y);
                } else {
                    mma16(co0 + nt * 4, a2h0, fh.x, fh.y);
                    mma16(co1 + nt * 4, a2h1, fh.x, fh.y);
                }
                mma16(co0 + nt * 4, a2h0, fl.x, fl.y);
                mma16(co0 + nt * 4, a2l0, fh.x, fh.y);
                mma16(co1 + nt * 4, a2h1, fl.x, fl.y);
                mma16(co1 + nt * 4, a2l1, fh.x, fh.y);
            }
        }
        #undef GEMM1_NT2

        // ---- epilogue per block: RMS scale + max-free softmax + store ----
        #define EPILOG(co, ssa, ssb, ra, pa, pb) do {                          \
            float sa = ssa, sb = ssb;                                          \
            sa += __shfl_xor_sync(0xffffffffu, sa, 1);                         \
            sa += __shfl_xor_sync(0xffffffffu, sa, 2);                         \
            sb += __shfl_xor_sync(0xffffffffu, sb, 1);                         \
            sb += __shfl_xor_sync(0xffffffffu, sb, 2);                         \
            float sc0 = rsqrtf(sa * (1.0f / 64.0f) + NORM_EPS) * L2E;          \
            float sc1 = rsqrtf(sb * (1.0f / 64.0f) + NORM_EPS) * L2E;          \
            float lg0[8], lg1[8];                                              \
            float s0 = 0.f, s1 = 0.f;                                          \
            _Pragma("unroll")                                                  \
            for (int nt = 0; nt < 4; nt++) {                                   \
                lg0[nt * 2]     = ex2f(co[nt * 4 + 0] * sc0);                  \
                lg0[nt * 2 + 1] = ex2f(co[nt * 4 + 1] * sc0);                  \
                lg1[nt * 2]     = ex2f(co[nt * 4 + 2] * sc1);                  \
                lg1[nt * 2 + 1] = ex2f(co[nt * 4 + 3] * sc1);                  \
            }                                                                  \
            _Pragma("unroll")                                                  \
            for (int i = 0; i < 8; i++) { s0 += lg0[i]; s1 += lg1[i]; }        \
            s0 += __shfl_xor_sync(0xffffffffu, s0, 1);                         \
            s0 += __shfl_xor_sync(0xffffffffu, s0, 2);                         \
            s1 += __shfl_xor_sync(0xffffffffu, s1, 1);                         \
            s1 += __shfl_xor_sync(0xffffffffu, s1, 2);                         \
            float i0 = rcpf(s0), i1 = rcpf(s1);                                \
            if (pa) {                                                          \
                float* o0 = out + (size_t)(ra) * 32 + 2 * q;                   \
                _Pragma("unroll")                                              \
                for (int nt = 0; nt < 4; nt++)                                 \
                    *(float2*)(o0 + nt * 8) =                                  \
                        make_float2(lg0[nt*2] * i0, lg0[nt*2+1] * i0);         \
            }                                                                  \
            if (pb) {                                                          \
                float* o1 = out + (size_t)(ra + 8) * 32 + 2 * q;               \
                _Pragma("unroll")                                              \
                for (int nt = 0; nt < 4; nt++)                                 \
                    *(float2*)(o1 + nt * 8) =                                  \
                        make_float2(lg1[nt*2] * i1, lg1[nt*2+1] * i1);         \
            }                                                                  \
        } while (0)
        EPILOG(co0, ssA0, ssA1, r0, p0, p1);
        EPILOG(co1, ssB0, ssB1, r2, p2, p3);
        #undef EPILOG
    }
}

// ---------------- launch ----------------
extern "C" void kernel_launch(void* const* d_in, const int* in_sizes, int n_in,
                              void* d_out, int out_size)
{
    const float* x         = (const float*)d_in[0];
    const float* f_out_w   = (const float*)d_in[1];
    const float* f_out_b   = (const float*)d_in[2];
    const float* in_proj_w = (const float*)d_in[3];
    const float* conv_w    = (const float*)d_in[4];
    const float* conv_b    = (const float*)d_in[5];
    const float* dt_bias   = (const float*)d_in[6];
    // d_in[7] = A_log (unused by the reference math)
    const float* D_skip    = (const float*)d_in[8];
    const float* norm_w    = (const float*)d_in[9];
    const float* out_proj_w= (const float*)d_in[10];

    int N = in_sizes[0] / IN_DIM;

    prep_kernel<<<48, 128>>>(f_out_w, f_out_b, in_proj_w, conv_w, conv_b,
                             dt_bias, D_skip, norm_w, out_proj_w);

    mamba_hmma_kernel<<<296, 256>>>(x, (float*)d_out, N);
}

// round 13
// speedup vs baseline: 1.0511x; 1.0511x over previous
#include <cuda_runtime.h>
#include <cuda_bf16.h>
#include <math.h>
#include <stdint.h>

// ---------------- problem constants ----------------
#define IN_DIM   36
#define NORM_EPS 1e-5f
#define L2E      1.4426950408889634f

// folded fp32 params from prep_kernel
#define P_W1   0        // 152*36 : (in_proj @ f_out_w), conv scale folded into rows 64..143
#define P_WOUT 5472     // 64*32  : [d][o] = out_proj[o][d]*norm_w[d]
#define P_B1   7520     // 152    : fully folded biases
#define P_DSK  7840     // 8
#define P_TOTAL 7848

__device__ float g_params[P_TOTAL];

// k16 fragment table: W1 recs idx = nt*4 + kk*2 + m  (nt<19, kk<2)  -> 76
//                     W2 recs idx = 76 + nt*8 + kk*2 + m (nt<4,kk<4) -> 32
#define NREC16 108
// fused-tail table (one uint2 rec per W1 n-tile, carries bias in k12/k13): 19
#define NTAIL  19

// ---------------- helpers ----------------
__device__ __forceinline__ uint32_t pk2(float a, float b) {   // lo=a, hi=b
    uint32_t r;
    asm("cvt.rn.bf16x2.f32 %0, %1, %2;" : "=r"(r) : "f"(b), "f"(a));
    return r;
}
__device__ __forceinline__ float lo16f(uint32_t p) { return __uint_as_float(p << 16); }
__device__ __forceinline__ float hi16f(uint32_t p) { return __uint_as_float(p & 0xffff0000u); }

__device__ __forceinline__ void mma16(float* c, const uint32_t* a,
                                      uint32_t b0, uint32_t b1) {
    asm volatile(
        "mma.sync.aligned.m16n8k16.row.col.f32.bf16.bf16.f32 "
        "{%0,%1,%2,%3}, {%4,%5,%6,%7}, {%8,%9}, {%0,%1,%2,%3};"
        : "+f"(c[0]), "+f"(c[1]), "+f"(c[2]), "+f"(c[3])
        : "r"(a[0]), "r"(a[1]), "r"(a[2]), "r"(a[3]), "r"(b0), "r"(b1));
}
// first MMA of an accumulator: D = A*B + 0 (no init movs; C = zeros -> RZ)
__device__ __forceinline__ void mma16_init(float* c, const uint32_t* a,
                                           uint32_t b0, uint32_t b1) {
    asm volatile(
        "mma.sync.aligned.m16n8k16.row.col.f32.bf16.bf16.f32 "
        "{%0,%1,%2,%3}, {%4,%5,%6,%7}, {%8,%9}, {%10,%10,%10,%10};"
        : "=f"(c[0]), "=f"(c[1]), "=f"(c[2]), "=f"(c[3])
        : "r"(a[0]), "r"(a[1]), "r"(a[2]), "r"(a[3]), "r"(b0), "r"(b1),
          "f"(0.0f));
}

__device__ __forceinline__ float rcpf(float v) {
    float r; asm("rcp.approx.f32 %0, %1;" : "=f"(r) : "f"(v)); return r;
}
__device__ __forceinline__ float ex2f(float v) {
    float r; asm("ex2.approx.f32 %0, %1;" : "=f"(r) : "f"(v)); return r;
}
// denominator of silu(a)*silu(b): (1+e^-a)(1+e^-b)
__device__ __forceinline__ float silu_den(float a, float b) {
    return (1.0f + __expf(-a)) * (1.0f + __expf(-b));
}
__device__ __forceinline__ float softplus1(float v) {
    return fmaxf(v, 0.0f) + __logf(1.0f + __expf(-fabsf(v)));
}

// ---------------- prep: fold weights on device ----------------
__global__ void prep_kernel(const float* __restrict__ f_out_w,
                            const float* __restrict__ f_out_b,
                            const float* __restrict__ in_proj_w,
                            const float* __restrict__ conv_w,
                            const float* __restrict__ conv_b,
                            const float* __restrict__ dt_bias,
                            const float* __restrict__ D_skip,
                            const float* __restrict__ norm_w,
                            const float* __restrict__ out_proj_w)
{
    int t = blockIdx.x * blockDim.x + threadIdx.x;
    int stride = gridDim.x * blockDim.x;
    // W1 rows: 0..63 z | 64..127 x | 128..135 B | 136..143 C | 144..151 dt
    for (int i = t; i < 152 * 36; i += stride) {
        int j = i / 36, k = i % 36;
        float s = 0.0f;
        #pragma unroll
        for (int m = 0; m < 32; m++) s += in_proj_w[j * 32 + m] * f_out_w[m * 36 + k];
        float scale = (j >= 64 && j < 144) ? conv_w[(j - 64) * 2 + 1] : 1.0f;
        g_params[P_W1 + i] = s * scale;
    }
    for (int i = t; i < 64 * 32; i += stride) {
        int d = i / 32, o = i % 32;
        g_params[P_WOUT + i] = out_proj_w[o * 64 + d] * norm_w[d];
    }
    for (int i = t; i < 152; i += stride) {
        float s = 0.0f;
        #pragma unroll
        for (int m = 0; m < 32; m++) s += in_proj_w[i * 32 + m] * f_out_b[m];
        float b;
        if (i < 64)       b = s;
        else if (i < 144) b = s * conv_w[(i - 64) * 2 + 1] + conv_b[i - 64];
        else              b = s + dt_bias[i - 144];
        g_params[P_B1 + i] = b;
    }
    for (int i = t; i < 8; i += stride) g_params[P_DSK + i] = D_skip[i];
}

// ---------------- main kernel: warp-MMA, register-resident ----------------
__global__ __launch_bounds__(256, 3)
void mamba_hmma_kernel(const float* __restrict__ x,
                       float* __restrict__ out, int N)
{
    __shared__ uint2    s_frag [NREC16 * 32];   // 27.6 KB
    __shared__ uint2    s_ftail[NTAIL  * 32];   // 4.75 KB (fused tail + bias)
    __shared__ float    s_dsk[8];
    __shared__ float    s_coef[8][16][8];       // [warp][row][head]

    const int tid  = threadIdx.x;
    const int lane = tid & 31;
    const int q    = lane & 3;
    const int g    = lane >> 2;
    const int w    = tid >> 5;

    // ---- build k16 fragment table ----
    for (int idx = tid; idx < NREC16 * 32; idx += 256) {
        int rec = idx >> 5, ln = idx & 31;
        int lq = ln & 3, lg = ln >> 2;
        float v0, v1, v2, v3;
        int m;
        if (rec < 76) {
            int nt = rec >> 2, rem = rec & 3;
            int kk = rem >> 1; m = rem & 1;
            int ch = nt * 8 + lg;
            int k0 = kk * 16 + 2 * lq;
            const float* wr = g_params + P_W1 + ch * 36;
            v0 = wr[k0]; v1 = wr[k0 + 1]; v2 = wr[k0 + 8]; v3 = wr[k0 + 9];
        } else {
            int r2 = rec - 76;
            int nt = r2 >> 3, rem = r2 & 7;
            int kk = rem >> 1; m = rem & 1;
            int o = nt * 8 + lg;
            int k0 = kk * 16 + 2 * lq;
            const float* w2 = g_params + P_WOUT;
            v0 = w2[(k0    ) * 32 + o];
            v1 = w2[(k0 + 1) * 32 + o];
            v2 = w2[(k0 + 8) * 32 + o];
            v3 = w2[(k0 + 9) * 32 + o];
        }
        uint32_t h01 = pk2(v0, v1), h23 = pk2(v2, v3);
        uint32_t r0, r1;
        if (m == 0) { r0 = h01; r1 = h23; }
        else {
            r0 = pk2(v0 - lo16f(h01), v1 - hi16f(h01));
            r1 = pk2(v2 - lo16f(h23), v3 - hi16f(h23));
        }
        s_frag[idx] = make_uint2(r0, r1);
    }
    // ---- fused-tail table ----
    // b0 (k 0..7):  lq<2 -> Wh_t   ; lq>=2 -> Wl_t
    // b1 (k 8..15): lq<2 -> Wh_t   ; lq==2 -> (bh,bl) bias ; lq==3 -> 0
    for (int idx = tid; idx < NTAIL * 32; idx += 256) {
        int nt = idx >> 5, ln = idx & 31;
        int lq = ln & 3, lg = ln >> 2;
        const float* wr = g_params + P_W1 + (nt * 8 + lg) * 36;
        int i = (lq & 1) * 2;
        float v0 = wr[32 + i], v1 = wr[33 + i];
        uint32_t h = pk2(v0, v1);
        uint32_t l = pk2(v0 - lo16f(h), v1 - hi16f(h));
        float b = g_params[P_B1 + nt * 8 + lg];
        uint32_t bh = pk2(b, 0.f);
        uint32_t bias = pk2(lo16f(bh), b - lo16f(bh));   // (bh, bl)
        uint32_t b0 = (lq < 2) ? h : l;
        uint32_t b1 = (lq < 2) ? h : ((lq == 2) ? bias : 0u);
        s_ftail[idx] = make_uint2(b0, b1);
    }
    if (tid < 8) s_dsk[tid] = g_params[P_DSK + tid];
    __syncthreads();

    const int warp_global = blockIdx.x * 8 + w;
    const int nwarps = gridDim.x * 8;
    const int nchunks = (N + 15) >> 4;
    const uint32_t ones2 = pk2(1.0f, 1.0f);

    for (int chk = warp_global; chk < nchunks; chk += nwarps) {
        const int r0 = (chk << 4) + g;
        const int r1 = r0 + 8;
        const bool p0 = r0 < N, p1 = r1 < N;
        const float* rp0 = x + (size_t)r0 * IN_DIM;
        const float* rp1 = x + (size_t)r1 * IN_DIM;

        // ---- A1 fragments: split-bf16 of x rows r0, r1 (k = 0..31) ----
        uint32_t ah[8], al[8];
        #pragma unroll
        for (int kk = 0; kk < 2; kk++) {
            int c  = kk * 16 + 2 * q;
            int c2 = c + 8;
            float2 x00 = p0 ? *(const float2*)(rp0 + c)  : make_float2(0.f, 0.f);
            float2 x10 = p1 ? *(const float2*)(rp1 + c)  : make_float2(0.f, 0.f);
            float2 x02 = p0 ? *(const float2*)(rp0 + c2) : make_float2(0.f, 0.f);
            float2 x12 = p1 ? *(const float2*)(rp1 + c2) : make_float2(0.f, 0.f);
            uint32_t h;
            h = pk2(x00.x, x00.y); ah[kk*4+0] = h;
            al[kk*4+0] = pk2(x00.x - lo16f(h), x00.y - hi16f(h));
            h = pk2(x10.x, x10.y); ah[kk*4+1] = h;
            al[kk*4+1] = pk2(x10.x - lo16f(h), x10.y - hi16f(h));
            h = pk2(x02.x, x02.y); ah[kk*4+2] = h;
            al[kk*4+2] = pk2(x02.x - lo16f(h), x02.y - hi16f(h));
            h = pk2(x12.x, x12.y); ah[kk*4+3] = h;
            al[kk*4+3] = pk2(x12.x - lo16f(h), x12.y - hi16f(h));
        }
        // ---- fused tail A-frag (k = 32..35 + bias-one lanes) ----
        // a0/a1 (k 0..7): xh_t ; a2/a3 (k 8..15): q<2 -> xl_t, q==2 -> (1,1), q==3 -> 0
        uint32_t at[4];
        {
            int c = 32 + ((q & 1) << 1);
            float2 x0 = p0 ? *(const float2*)(rp0 + c) : make_float2(0.f, 0.f);
            float2 x1 = p1 ? *(const float2*)(rp1 + c) : make_float2(0.f, 0.f);
            uint32_t h0 = pk2(x0.x, x0.y);
            uint32_t h1 = pk2(x1.x, x1.y);
            at[0] = h0;
            at[1] = h1;
            uint32_t l0 = pk2(x0.x - lo16f(h0), x0.y - hi16f(h0));
            uint32_t l1 = pk2(x1.x - lo16f(h1), x1.y - hi16f(h1));
            at[2] = (q < 2) ? l0 : ((q == 2) ? ones2 : 0u);
            at[3] = (q < 2) ? l1 : ((q == 2) ? ones2 : 0u);
        }

        // GEMM1 for one n-tile: TWO independent accumulator chains
        //   cA: tail-init -> chunk0 x3   (depth 4)
        //   cB: chunk1-init -> x2        (depth 3)
        // then c = cA + cB (4 FADD). Same products, shorter critical path.
        #define GEMM1_NT(nt, c) do {                                          \
            float cA_[4], cB_[4];                                             \
            {                                                                 \
                uint2 ft = s_ftail[(nt) * 32 + lane];                         \
                mma16_init(cA_, at, ft.x, ft.y);                              \
            }                                                                 \
            {                                                                 \
                uint2 fh = s_frag[((nt) * 4 + 0) * 32 + lane];                \
                uint2 fl = s_frag[((nt) * 4 + 1) * 32 + lane];                \
                mma16(cA_, ah, fh.x, fh.y);                                   \
                mma16(cA_, ah, fl.x, fl.y);                                   \
                mma16(cA_, al, fh.x, fh.y);                                   \
            }                                                                 \
            {                                                                 \
                uint2 fh = s_frag[((nt) * 4 + 2) * 32 + lane];                \
                uint2 fl = s_frag[((nt) * 4 + 3) * 32 + lane];                \
                mma16_init(cB_, ah + 4, fh.x, fh.y);                          \
                mma16(cB_, ah + 4, fl.x, fl.y);                               \
                mma16(cB_, al + 4, fh.x, fh.y);                               \
            }                                                                 \
            c[0] = cA_[0] + cB_[0];                                           \
            c[1] = cA_[1] + cB_[1];                                           \
            c[2] = cA_[2] + cB_[2];                                           \
            c[3] = cA_[3] + cB_[3];                                           \
        } while (0)

        // ---- B, C, dt n-tiles (16,17,18) ----
        float cB[4], cC[4], cD[4];
        GEMM1_NT(16, cB);
        GEMM1_NT(17, cC);
        GEMM1_NT(18, cD);

        // bc per row: 4 silu-pairs, ONE rcp (batched inverse)
        float pr0, pr1;
        {
            float n0 = cB[0] * cC[0], n1 = cB[1] * cC[1];
            float n2 = cB[2] * cC[2], n3 = cB[3] * cC[3];
            float d0 = silu_den(cB[0], cC[0]);
            float d1 = silu_den(cB[1], cC[1]);
            float d2 = silu_den(cB[2], cC[2]);
            float d3 = silu_den(cB[3], cC[3]);
            float p01 = d0 * d1, p23 = d2 * d3;
            float r = rcpf(p01 * p23);
            float r01 = r * p23, r23 = r * p01;
            pr0 = n0 * (d1 * r01) + n1 * (d0 * r01);
            pr1 = n2 * (d3 * r23) + n3 * (d2 * r23);
        }
        pr0 += __shfl_xor_sync(0xffffffffu, pr0, 1);
        pr0 += __shfl_xor_sync(0xffffffffu, pr0, 2);
        pr1 += __shfl_xor_sync(0xffffffffu, pr1, 1);
        pr1 += __shfl_xor_sync(0xffffffffu, pr1, 2);

        // coef[head] = softplus(dt)*bc + D_skip  -> shared scratch (per warp)
        {
            float dsk0 = s_dsk[2 * q], dsk1 = s_dsk[2 * q + 1];
            float k00 = softplus1(cD[0]) * pr0 + dsk0;
            float k01 = softplus1(cD[1]) * pr0 + dsk1;
            float k10 = softplus1(cD[2]) * pr1 + dsk0;
            float k11 = softplus1(cD[3]) * pr1 + dsk1;
            __syncwarp();
            *(float2*)&s_coef[w][g][2 * q]     = make_float2(k00, k01);
            *(float2*)&s_coef[w][g + 8][2 * q] = make_float2(k10, k11);
            __syncwarp();
        }

        // ---- z/x n-tiles -> gated y -> GEMM2 (interleaved per 16-ch chunk) ----
        float co[16];
        float ss0 = 0.0f, ss1 = 0.0f;

        #pragma unroll
        for (int t = 0; t < 4; t++) {
            uint32_t a2h[4], a2l[4];
            #pragma unroll
            for (int u = 0; u < 2; u++) {
                const int j = 2 * t + u;
                float cz[4], cx[4];
                GEMM1_NT(j, cz);
                GEMM1_NT(8 + j, cx);
                float cf0 = s_coef[w][g][j];
                float cf1 = s_coef[w][g + 8][j];
                // 4 silu-pairs, ONE rcp
                float n0 = cx[0] * cz[0] * cf0, n1 = cx[1] * cz[1] * cf0;
                float n2 = cx[2] * cz[2] * cf1, n3 = cx[3] * cz[3] * cf1;
                float d0 = silu_den(cx[0], cz[0]);
                float d1 = silu_den(cx[1], cz[1]);
                float d2 = silu_den(cx[2], cz[2]);
                float d3 = silu_den(cx[3], cz[3]);
                float p01 = d0 * d1, p23 = d2 * d3;
                float r = rcpf(p01 * p23);
                float r01 = r * p23, r23 = r * p01;
                float y00 = n0 * (d1 * r01);
                float y01 = n1 * (d0 * r01);
                float y10 = n2 * (d3 * r23);
                float y11 = n3 * (d2 * r23);
                ss0 += y00 * y00 + y01 * y01;
                ss1 += y10 * y10 + y11 * y11;
                uint32_t h0 = pk2(y00, y01), h1 = pk2(y10, y11);
                a2h[2*u]     = h0;
                a2h[2*u + 1] = h1;
                a2l[2*u]     = pk2(y00 - lo16f(h0), y01 - hi16f(h0));
                a2l[2*u + 1] = pk2(y10 - lo16f(h1), y11 - hi16f(h1));
            }
            #pragma unroll
            for (int nt = 0; nt < 4; nt++) {
                uint2 fh = s_frag[(76 + nt * 8 + t * 2 + 0) * 32 + lane];
                uint2 fl = s_frag[(76 + nt * 8 + t * 2 + 1) * 32 + lane];
                if (t == 0) mma16_init(co + nt * 4, a2h, fh.x, fh.y);
                else        mma16(co + nt * 4, a2h, fh.x, fh.y);
                mma16(co + nt * 4, a2h, fl.x, fl.y);
                mma16(co + nt * 4, a2l, fh.x, fh.y);
            }
        }
        #undef GEMM1_NT

        ss0 += __shfl_xor_sync(0xffffffffu, ss0, 1);
        ss0 += __shfl_xor_sync(0xffffffffu, ss0, 2);
        ss1 += __shfl_xor_sync(0xffffffffu, ss1, 1);
        ss1 += __shfl_xor_sync(0xffffffffu, ss1, 2);
        // fold log2(e) into the RMS scale: softmax done in ex2 domain
        float sc0 = rsqrtf(ss0 * (1.0f / 64.0f) + NORM_EPS) * L2E;
        float sc1 = rsqrtf(ss1 * (1.0f / 64.0f) + NORM_EPS) * L2E;

        // ---- softmax over 32, max-free (|logit| <= ~11 -> ex2 args bounded) ----
        float lg0[8], lg1[8];
        float s0 = 0.f, s1 = 0.f;
        #pragma unroll
        for (int nt = 0; nt < 4; nt++) {
            lg0[nt * 2]     = ex2f(co[nt * 4 + 0] * sc0);
            lg0[nt * 2 + 1] = ex2f(co[nt * 4 + 1] * sc0);
            lg1[nt * 2]     = ex2f(co[nt * 4 + 2] * sc1);
            lg1[nt * 2 + 1] = ex2f(co[nt * 4 + 3] * sc1);
        }
        #pragma unroll
        for (int i = 0; i < 8; i++) { s0 += lg0[i]; s1 += lg1[i]; }
        s0 += __shfl_xor_sync(0xffffffffu, s0, 1);
        s0 += __shfl_xor_sync(0xffffffffu, s0, 2);
        s1 += __shfl_xor_sync(0xffffffffu, s1, 1);
        s1 += __shfl_xor_sync(0xffffffffu, s1, 2);
        float i0 = rcpf(s0), i1 = rcpf(s1);

        if (p0) {
            float* o0 = out + (size_t)r0 * 32 + 2 * q;
            #pragma unroll
            for (int nt = 0; nt < 4; nt++)
                *(float2*)(o0 + nt * 8) = make_float2(lg0[nt*2] * i0, lg0[nt*2+1] * i0);
        }
        if (p1) {
            float* o1 = out + (size_t)r1 * 32 + 2 * q;
            #pragma unroll
            for (int nt = 0; nt < 4; nt++)
                *(float2*)(o1 + nt * 8) = make_float2(lg1[nt*2] * i1, lg1[nt*2+1] * i1);
        }
    }
}

// ---------------- launch ----------------
extern "C" void kernel_launch(void* const* d_in, const int* in_sizes, int n_in,
                              void* d_out, int out_size)
{
    const float* x         = (const float*)d_in[0];
    const float* f_out_w   = (const float*)d_in[1];
    const float* f_out_b   = (const float*)d_in[2];
    const float* in_proj_w = (const float*)d_in[3];
    const float* conv_w    = (const float*)d_in[4];
    const float* conv_b    = (const float*)d_in[5];
    const float* dt_bias   = (const float*)d_in[6];
    // d_in[7] = A_log (unused by the reference math)
    const float* D_skip    = (const float*)d_in[8];
    const float* norm_w    = (const float*)d_in[9];
    const float* out_proj_w= (const float*)d_in[10];

    int N = in_sizes[0] / IN_DIM;

    prep_kernel<<<48, 128>>>(f_out_w, f_out_b, in_proj_w, conv_w, conv_b,
                             dt_bias, D_skip, norm_w, out_proj_w);

    mamba_hmma_kernel<<<444, 256>>>(x, (float*)d_out, N);
}

// round 14
// speedup vs baseline: 1.1692x; 1.1124x over previous
#include <cuda_runtime.h>
#include <cuda_bf16.h>
#include <cuda_fp16.h>
#include <math.h>
#include <stdint.h>

// ---------------- problem constants ----------------
#define IN_DIM   36
#define NORM_EPS 1e-5f
#define L2E      1.4426950408889634f

// folded fp32 params from prep_kernel
#define P_W1   0        // 152*36 : (in_proj @ f_out_w), conv scale folded into rows 64..143
#define P_WOUT 5472     // 64*32  : [d][o] = out_proj[o][d]*norm_w[d]
#define P_B1   7520     // 152    : fully folded biases
#define P_DSK  7840     // 8
#define P_TOTAL 7848

__device__ float g_params[P_TOTAL];

// GEMM1 fp16 table: rec = nt*5 + c  (nt<19, c<5)  -> 95 uint2 recs
//   K=80 concat: S/T[i]: i<36 Wh[i]; 36..39 zero; 40..75 Wh[i-40]; 76 bh; 77 bl; 78,79 zero
#define NREC1  95
// GEMM2 bf16 table: rec = nt*8 + t*2 + m (nt<4, t<4, m<2) -> 32 uint2 recs
#define NREC2  32

// ---------------- helpers ----------------
__device__ __forceinline__ uint32_t pk2(float a, float b) {   // bf16x2, lo=a hi=b
    uint32_t r;
    asm("cvt.rn.bf16x2.f32 %0, %1, %2;" : "=r"(r) : "f"(b), "f"(a));
    return r;
}
__device__ __forceinline__ float lo16f(uint32_t p) { return __uint_as_float(p << 16); }
__device__ __forceinline__ float hi16f(uint32_t p) { return __uint_as_float(p & 0xffff0000u); }

__device__ __forceinline__ uint32_t pkh2(float a, float b) {  // f16x2, lo=a hi=b
    uint32_t r;
    asm("cvt.rn.f16x2.f32 %0, %1, %2;" : "=r"(r) : "f"(b), "f"(a));
    return r;
}
__device__ __forceinline__ float2 h2f2(uint32_t p) {          // unpack f16x2 -> 2 floats
    float lo, hi;
    asm("{.reg .b16 l, h;\n"
        " mov.b32 {l, h}, %2;\n"
        " cvt.f32.f16 %0, l;\n"
        " cvt.f32.f16 %1, h;}"
        : "=f"(lo), "=f"(hi) : "r"(p));
    return make_float2(lo, hi);
}

// bf16 mma (GEMM2)
__device__ __forceinline__ void mma16(float* c, const uint32_t* a,
                                      uint32_t b0, uint32_t b1) {
    asm volatile(
        "mma.sync.aligned.m16n8k16.row.col.f32.bf16.bf16.f32 "
        "{%0,%1,%2,%3}, {%4,%5,%6,%7}, {%8,%9}, {%0,%1,%2,%3};"
        : "+f"(c[0]), "+f"(c[1]), "+f"(c[2]), "+f"(c[3])
        : "r"(a[0]), "r"(a[1]), "r"(a[2]), "r"(a[3]), "r"(b0), "r"(b1));
}
__device__ __forceinline__ void mma16_init(float* c, const uint32_t* a,
                                           uint32_t b0, uint32_t b1) {
    asm volatile(
        "mma.sync.aligned.m16n8k16.row.col.f32.bf16.bf16.f32 "
        "{%0,%1,%2,%3}, {%4,%5,%6,%7}, {%8,%9}, {%10,%10,%10,%10};"
        : "=f"(c[0]), "=f"(c[1]), "=f"(c[2]), "=f"(c[3])
        : "r"(a[0]), "r"(a[1]), "r"(a[2]), "r"(a[3]), "r"(b0), "r"(b1),
          "f"(0.0f));
}
// fp16 mma (GEMM1)
__device__ __forceinline__ void mma16f(float* c, const uint32_t* a,
                                       uint32_t b0, uint32_t b1) {
    asm volatile(
        "mma.sync.aligned.m16n8k16.row.col.f32.f16.f16.f32 "
        "{%0,%1,%2,%3}, {%4,%5,%6,%7}, {%8,%9}, {%0,%1,%2,%3};"
        : "+f"(c[0]), "+f"(c[1]), "+f"(c[2]), "+f"(c[3])
        : "r"(a[0]), "r"(a[1]), "r"(a[2]), "r"(a[3]), "r"(b0), "r"(b1));
}
__device__ __forceinline__ void mma16f_init(float* c, const uint32_t* a,
                                            uint32_t b0, uint32_t b1) {
    asm volatile(
        "mma.sync.aligned.m16n8k16.row.col.f32.f16.f16.f32 "
        "{%0,%1,%2,%3}, {%4,%5,%6,%7}, {%8,%9}, {%10,%10,%10,%10};"
        : "=f"(c[0]), "=f"(c[1]), "=f"(c[2]), "=f"(c[3])
        : "r"(a[0]), "r"(a[1]), "r"(a[2]), "r"(a[3]), "r"(b0), "r"(b1),
          "f"(0.0f));
}

__device__ __forceinline__ float rcpf(float v) {
    float r; asm("rcp.approx.f32 %0, %1;" : "=f"(r) : "f"(v)); return r;
}
__device__ __forceinline__ float ex2f(float v) {
    float r; asm("ex2.approx.f32 %0, %1;" : "=f"(r) : "f"(v)); return r;
}
__device__ __forceinline__ float silu_den(float a, float b) {
    return (1.0f + __expf(-a)) * (1.0f + __expf(-b));
}
__device__ __forceinline__ float softplus1(float v) {
    return fmaxf(v, 0.0f) + __logf(1.0f + __expf(-fabsf(v)));
}

// ---------------- prep: fold weights on device ----------------
__global__ void prep_kernel(const float* __restrict__ f_out_w,
                            const float* __restrict__ f_out_b,
                            const float* __restrict__ in_proj_w,
                            const float* __restrict__ conv_w,
                            const float* __restrict__ conv_b,
                            const float* __restrict__ dt_bias,
                            const float* __restrict__ D_skip,
                            const float* __restrict__ norm_w,
                            const float* __restrict__ out_proj_w)
{
    int t = blockIdx.x * blockDim.x + threadIdx.x;
    int stride = gridDim.x * blockDim.x;
    // W1 rows: 0..63 z | 64..127 x | 128..135 B | 136..143 C | 144..151 dt
    for (int i = t; i < 152 * 36; i += stride) {
        int j = i / 36, k = i % 36;
        float s = 0.0f;
        #pragma unroll
        for (int m = 0; m < 32; m++) s += in_proj_w[j * 32 + m] * f_out_w[m * 36 + k];
        float scale = (j >= 64 && j < 144) ? conv_w[(j - 64) * 2 + 1] : 1.0f;
        g_params[P_W1 + i] = s * scale;
    }
    for (int i = t; i < 64 * 32; i += stride) {
        int d = i / 32, o = i % 32;
        g_params[P_WOUT + i] = out_proj_w[o * 64 + d] * norm_w[d];
    }
    for (int i = t; i < 152; i += stride) {
        float s = 0.0f;
        #pragma unroll
        for (int m = 0; m < 32; m++) s += in_proj_w[i * 32 + m] * f_out_b[m];
        float b;
        if (i < 64)       b = s;
        else if (i < 144) b = s * conv_w[(i - 64) * 2 + 1] + conv_b[i - 64];
        else              b = s + dt_bias[i - 144];
        g_params[P_B1 + i] = b;
    }
    for (int i = t; i < 8; i += stride) g_params[P_DSK + i] = D_skip[i];
}

// ---------------- main kernel: warp-MMA, register-resident ----------------
__global__ __launch_bounds__(256, 3)
void mamba_hmma_kernel(const float* __restrict__ x,
                       float* __restrict__ out, int N)
{
    __shared__ uint2    s_frag1[NREC1 * 32];    // 24.3 KB (fp16 W1, K=80 concat)
    __shared__ uint2    s_frag2[NREC2 * 32];    // 8.2 KB (bf16 W2, 3-term)
    __shared__ float    s_dsk[8];
    __shared__ float    s_coef[8][16][8];       // [warp][row][head]

    const int tid  = threadIdx.x;
    const int lane = tid & 31;
    const int q    = lane & 3;
    const int g    = lane >> 2;
    const int w    = tid >> 5;

    // ---- build GEMM1 fp16 table ----
    for (int idx = tid; idx < NREC1 * 32; idx += 256) {
        int rec = idx >> 5, ln = idx & 31;
        int lq = ln & 3, lg = ln >> 2;
        int nt = rec / 5, c = rec - nt * 5;
        int ch = nt * 8 + lg;
        const float* wr = g_params + P_W1 + ch * 36;
        float b = g_params[P_B1 + ch];
        float bhf = __half2float(__float2half_rn(b));
        // T[i] of the K=80 concat
        auto T = [&](int i) -> float {
            if (i < 36)  return __half2float(__float2half_rn(wr[i]));
            if (i < 40)  return 0.0f;
            if (i < 76)  return __half2float(__float2half_rn(wr[i - 40]));
            if (i == 76) return bhf;
            if (i == 77) return b - bhf;   // pkh2 rounds -> bl
            return 0.0f;
        };
        int k0 = 16 * c + 2 * lq;
        int k1 = 16 * c + 8 + 2 * lq;
        s_frag1[idx] = make_uint2(pkh2(T(k0), T(k0 + 1)),
                                  pkh2(T(k1), T(k1 + 1)));
    }
    // ---- build GEMM2 bf16 table (3-term split) ----
    for (int idx = tid; idx < NREC2 * 32; idx += 256) {
        int rec = idx >> 5, ln = idx & 31;
        int lq = ln & 3, lg = ln >> 2;
        int nt = rec >> 3, rem = rec & 7;
        int kk = rem >> 1, m = rem & 1;
        int o = nt * 8 + lg;
        int k0 = kk * 16 + 2 * lq;
        const float* w2 = g_params + P_WOUT;
        float v0 = w2[(k0    ) * 32 + o];
        float v1 = w2[(k0 + 1) * 32 + o];
        float v2 = w2[(k0 + 8) * 32 + o];
        float v3 = w2[(k0 + 9) * 32 + o];
        uint32_t h01 = pk2(v0, v1), h23 = pk2(v2, v3);
        uint32_t r0, r1;
        if (m == 0) { r0 = h01; r1 = h23; }
        else {
            r0 = pk2(v0 - lo16f(h01), v1 - hi16f(h01));
            r1 = pk2(v2 - lo16f(h23), v3 - hi16f(h23));
        }
        s_frag2[idx] = make_uint2(r0, r1);
    }
    if (tid < 8) s_dsk[tid] = g_params[P_DSK + tid];
    __syncthreads();

    const int warp_global = blockIdx.x * 8 + w;
    const int nwarps = gridDim.x * 8;
    const int nchunks = (N + 15) >> 4;
    const uint32_t onesH = pkh2(1.0f, 1.0f);

    for (int chk = warp_global; chk < nchunks; chk += nwarps) {
        const int r0 = (chk << 4) + g;
        const int r1 = r0 + 8;
        const bool p0 = r0 < N, p1 = r1 < N;
        const float* rp0 = x + (size_t)r0 * IN_DIM;
        const float* rp1 = x + (size_t)r1 * IN_DIM;

        // ---- load x pairs and build fp16 two-level split ----
        // pairs at cols {2q, 8+2q, 16+2q, 24+2q} (+ {32+2q} for q<2)
        uint32_t XH[2][5], XL[2][5];
        #pragma unroll
        for (int i = 0; i < 4; i++) {
            int c = i * 8 + 2 * q;
            float2 v0 = p0 ? *(const float2*)(rp0 + c) : make_float2(0.f, 0.f);
            float2 v1 = p1 ? *(const float2*)(rp1 + c) : make_float2(0.f, 0.f);
            uint32_t h0 = pkh2(v0.x, v0.y), h1 = pkh2(v1.x, v1.y);
            float2 f0 = h2f2(h0), f1 = h2f2(h1);
            XH[0][i] = h0; XL[0][i] = pkh2(v0.x - f0.x, v0.y - f0.y);
            XH[1][i] = h1; XL[1][i] = pkh2(v1.x - f1.x, v1.y - f1.y);
        }
        if (q < 2) {
            int c = 32 + 2 * q;
            float2 v0 = p0 ? *(const float2*)(rp0 + c) : make_float2(0.f, 0.f);
            float2 v1 = p1 ? *(const float2*)(rp1 + c) : make_float2(0.f, 0.f);
            uint32_t h0 = pkh2(v0.x, v0.y), h1 = pkh2(v1.x, v1.y);
            float2 f0 = h2f2(h0), f1 = h2f2(h1);
            XH[0][4] = h0; XL[0][4] = pkh2(v0.x - f0.x, v0.y - f0.y);
            XH[1][4] = h1; XL[1][4] = pkh2(v1.x - f1.x, v1.y - f1.y);
        } else {
            XH[0][4] = 0u; XL[0][4] = (q == 2) ? onesH : 0u;
            XH[1][4] = 0u; XL[1][4] = (q == 2) ? onesH : 0u;
        }

        // ---- A fragments per K-chunk of the concat ----
        // c0: xh@2q | xh@8+2q      c1: xh@16+2q | xh@24+2q
        // c2: (q<2 ? xh@32+2q : 0) | xl@2q
        // c3: xl@8+2q | xl@16+2q   c4: xl@24+2q | (q<2 ? xl@32+2q : q==2 ones : 0)
        uint32_t A0[4] = { XH[0][0], XH[1][0], XH[0][1], XH[1][1] };
        uint32_t A1[4] = { XH[0][2], XH[1][2], XH[0][3], XH[1][3] };
        uint32_t A2[4] = { XH[0][4], XH[1][4], XL[0][0], XL[1][0] };
        uint32_t A3[4] = { XL[0][1], XL[1][1], XL[0][2], XL[1][2] };
        uint32_t A4[4] = { XL[0][3], XL[1][3], XL[0][4], XL[1][4] };

        // GEMM1 for one n-tile: 5 fp16 MMAs (bias carried at K=76/77)
        #define GEMM1_NT(nt, c) do {                                          \
            uint2 f0_ = s_frag1[((nt) * 5 + 0) * 32 + lane];                  \
            mma16f_init(c, A0, f0_.x, f0_.y);                                 \
            uint2 f1_ = s_frag1[((nt) * 5 + 1) * 32 + lane];                  \
            mma16f(c, A1, f1_.x, f1_.y);                                      \
            uint2 f2_ = s_frag1[((nt) * 5 + 2) * 32 + lane];                  \
            mma16f(c, A2, f2_.x, f2_.y);                                      \
            uint2 f3_ = s_frag1[((nt) * 5 + 3) * 32 + lane];                  \
            mma16f(c, A3, f3_.x, f3_.y);                                      \
            uint2 f4_ = s_frag1[((nt) * 5 + 4) * 32 + lane];                  \
            mma16f(c, A4, f4_.x, f4_.y);                                      \
        } while (0)

        // ---- B, C, dt n-tiles (16,17,18) ----
        float cB[4], cC[4], cD[4];
        GEMM1_NT(16, cB);
        GEMM1_NT(17, cC);
        GEMM1_NT(18, cD);

        // bc per row: 4 silu-pairs, ONE rcp (batched inverse)
        float pr0, pr1;
        {
            float n0 = cB[0] * cC[0], n1 = cB[1] * cC[1];
            float n2 = cB[2] * cC[2], n3 = cB[3] * cC[3];
            float d0 = silu_den(cB[0], cC[0]);
            float d1 = silu_den(cB[1], cC[1]);
            float d2 = silu_den(cB[2], cC[2]);
            float d3 = silu_den(cB[3], cC[3]);
            float p01 = d0 * d1, p23 = d2 * d3;
            float r = rcpf(p01 * p23);
            float r01 = r * p23, r23 = r * p01;
            pr0 = n0 * (d1 * r01) + n1 * (d0 * r01);
            pr1 = n2 * (d3 * r23) + n3 * (d2 * r23);
        }
        pr0 += __shfl_xor_sync(0xffffffffu, pr0, 1);
        pr0 += __shfl_xor_sync(0xffffffffu, pr0, 2);
        pr1 += __shfl_xor_sync(0xffffffffu, pr1, 1);
        pr1 += __shfl_xor_sync(0xffffffffu, pr1, 2);

        // coef[head] = softplus(dt)*bc + D_skip  -> shared scratch (per warp)
        {
            float dsk0 = s_dsk[2 * q], dsk1 = s_dsk[2 * q + 1];
            float k00 = softplus1(cD[0]) * pr0 + dsk0;
            float k01 = softplus1(cD[1]) * pr0 + dsk1;
            float k10 = softplus1(cD[2]) * pr1 + dsk0;
            float k11 = softplus1(cD[3]) * pr1 + dsk1;
            __syncwarp();
            *(float2*)&s_coef[w][g][2 * q]     = make_float2(k00, k01);
            *(float2*)&s_coef[w][g + 8][2 * q] = make_float2(k10, k11);
            __syncwarp();
        }

        // ---- z/x n-tiles -> gated y -> GEMM2 (interleaved per 16-ch chunk) ----
        float co[16];
        float ss0 = 0.0f, ss1 = 0.0f;

        #pragma unroll
        for (int t = 0; t < 4; t++) {
            uint32_t a2h[4], a2l[4];
            #pragma unroll
            for (int u = 0; u < 2; u++) {
                const int j = 2 * t + u;
                float cz[4], cx[4];
                GEMM1_NT(j, cz);
                GEMM1_NT(8 + j, cx);
                float cf0 = s_coef[w][g][j];
                float cf1 = s_coef[w][g + 8][j];
                // 4 silu-pairs, ONE rcp
                float n0 = cx[0] * cz[0] * cf0, n1 = cx[1] * cz[1] * cf0;
                float n2 = cx[2] * cz[2] * cf1, n3 = cx[3] * cz[3] * cf1;
                float d0 = silu_den(cx[0], cz[0]);
                float d1 = silu_den(cx[1], cz[1]);
                float d2 = silu_den(cx[2], cz[2]);
                float d3 = silu_den(cx[3], cz[3]);
                float p01 = d0 * d1, p23 = d2 * d3;
                float r = rcpf(p01 * p23);
                float r01 = r * p23, r23 = r * p01;
                float y00 = n0 * (d1 * r01);
                float y01 = n1 * (d0 * r01);
                float y10 = n2 * (d3 * r23);
                float y11 = n3 * (d2 * r23);
                ss0 += y00 * y00 + y01 * y01;
                ss1 += y10 * y10 + y11 * y11;
                uint32_t h0 = pk2(y00, y01), h1 = pk2(y10, y11);
                a2h[2*u]     = h0;
                a2h[2*u + 1] = h1;
                a2l[2*u]     = pk2(y00 - lo16f(h0), y01 - hi16f(h0));
                a2l[2*u + 1] = pk2(y10 - lo16f(h1), y11 - hi16f(h1));
            }
            #pragma unroll
            for (int nt = 0; nt < 4; nt++) {
                uint2 fh = s_frag2[(nt * 8 + t * 2 + 0) * 32 + lane];
                uint2 fl = s_frag2[(nt * 8 + t * 2 + 1) * 32 + lane];
                if (t == 0) mma16_init(co + nt * 4, a2h, fh.x, fh.y);
                else        mma16(co + nt * 4, a2h, fh.x, fh.y);
                mma16(co + nt * 4, a2h, fl.x, fl.y);
                mma16(co + nt * 4, a2l, fh.x, fh.y);
            }
        }
        #undef GEMM1_NT

        ss0 += __shfl_xor_sync(0xffffffffu, ss0, 1);
        ss0 += __shfl_xor_sync(0xffffffffu, ss0, 2);
        ss1 += __shfl_xor_sync(0xffffffffu, ss1, 1);
        ss1 += __shfl_xor_sync(0xffffffffu, ss1, 2);
        // fold log2(e) into the RMS scale: softmax done in ex2 domain
        float sc0 = rsqrtf(ss0 * (1.0f / 64.0f) + NORM_EPS) * L2E;
        float sc1 = rsqrtf(ss1 * (1.0f / 64.0f) + NORM_EPS) * L2E;

        // ---- softmax over 32, max-free (|logit| bounded -> ex2 args safe) ----
        float lg0[8], lg1[8];
        float s0 = 0.f, s1 = 0.f;
        #pragma unroll
        for (int nt = 0; nt < 4; nt++) {
            lg0[nt * 2]     = ex2f(co[nt * 4 + 0] * sc0);
            lg0[nt * 2 + 1] = ex2f(co[nt * 4 + 1] * sc0);
            lg1[nt * 2]     = ex2f(co[nt * 4 + 2] * sc1);
            lg1[nt * 2 + 1] = ex2f(co[nt * 4 + 3] * sc1);
        }
        #pragma unroll
        for (int i = 0; i < 8; i++) { s0 += lg0[i]; s1 += lg1[i]; }
        s0 += __shfl_xor_sync(0xffffffffu, s0, 1);
        s0 += __shfl_xor_sync(0xffffffffu, s0, 2);
        s1 += __shfl_xor_sync(0xffffffffu, s1, 1);
        s1 += __shfl_xor_sync(0xffffffffu, s1, 2);
        float i0 = rcpf(s0), i1 = rcpf(s1);

        if (p0) {
            float* o0 = out + (size_t)r0 * 32 + 2 * q;
            #pragma unroll
            for (int nt = 0; nt < 4; nt++)
                *(float2*)(o0 + nt * 8) = make_float2(lg0[nt*2] * i0, lg0[nt*2+1] * i0);
        }
        if (p1) {
            float* o1 = out + (size_t)r1 * 32 + 2 * q;
            #pragma unroll
            for (int nt = 0; nt < 4; nt++)
                *(float2*)(o1 + nt * 8) = make_float2(lg1[nt*2] * i1, lg1[nt*2+1] * i1);
        }
    }
}

// ---------------- launch ----------------
extern "C" void kernel_launch(void* const* d_in, const int* in_sizes, int n_in,
                              void* d_out, int out_size)
{
    const float* x         = (const float*)d_in[0];
    const float* f_out_w   = (const float*)d_in[1];
    const float* f_out_b   = (const float*)d_in[2];
    const float* in_proj_w = (const float*)d_in[3];
    const float* conv_w    = (const float*)d_in[4];
    const float* conv_b    = (const float*)d_in[5];
    const float* dt_bias   = (const float*)d_in[6];
    // d_in[7] = A_log (unused by the reference math)
    const float* D_skip    = (const float*)d_in[8];
    const float* norm_w    = (const float*)d_in[9];
    const float* out_proj_w= (const float*)d_in[10];

    int N = in_sizes[0] / IN_DIM;

    prep_kernel<<<48, 128>>>(f_out_w, f_out_b, in_proj_w, conv_w, conv_b,
                             dt_bias, D_skip, norm_w, out_proj_w);

    mamba_hmma_kernel<<<444, 256>>>(x, (float*)d_out, N);
}

// round 15
// speedup vs baseline: 1.2184x; 1.0421x over previous
#include <cuda_runtime.h>
#include <cuda_bf16.h>
#include <cuda_fp16.h>
#include <math.h>
#include <stdint.h>

// ---------------- problem constants ----------------
#define IN_DIM   36
#define NORM_EPS 1e-5f
#define L2E      1.4426950408889634f

// folded fp32 params from prep_kernel
#define P_W1   0        // 152*36 : (in_proj @ f_out_w), conv scale folded into rows 64..143
#define P_WOUT 5472     // 64*32  : [d][o] = out_proj[o][d]*norm_w[d]
#define P_B1   7520     // 152    : fully folded biases
#define P_DSK  7840     // 8
#define P_TOTAL 7848

__device__ float g_params[P_TOTAL];

// GEMM1 fp16 tables (K=80 concat: [Wh(36) | 0(4) | Wh(36) | bh bl | 0 0]):
//   s_frag1q: uint4 rec = nt*2 + p   (chunks c=2p, 2p+1)      -> 38 recs
//   s_frag1t: uint2 rec = nt         (chunk c=4, bias lanes)  -> 19 recs
#define NREC1Q 38
#define NREC1T 19
// GEMM2 fp16 table: uint2 rec = nt*4 + t (nt<4, t<4) -> 16 recs (shared by yh/yl)
#define NREC2  16

// ---------------- helpers ----------------
__device__ __forceinline__ uint32_t pkh2(float a, float b) {  // f16x2, lo=a hi=b
    uint32_t r;
    asm("cvt.rn.f16x2.f32 %0, %1, %2;" : "=r"(r) : "f"(b), "f"(a));
    return r;
}
__device__ __forceinline__ float2 h2f2(uint32_t p) {          // unpack f16x2 -> 2 floats
    float lo, hi;
    asm("{.reg .b16 l, h;\n"
        " mov.b32 {l, h}, %2;\n"
        " cvt.f32.f16 %0, l;\n"
        " cvt.f32.f16 %1, h;}"
        : "=f"(lo), "=f"(hi) : "r"(p));
    return make_float2(lo, hi);
}

// fp16 mma
__device__ __forceinline__ void mma16f(float* c, const uint32_t* a,
                                       uint32_t b0, uint32_t b1) {
    asm volatile(
        "mma.sync.aligned.m16n8k16.row.col.f32.f16.f16.f32 "
        "{%0,%1,%2,%3}, {%4,%5,%6,%7}, {%8,%9}, {%0,%1,%2,%3};"
        : "+f"(c[0]), "+f"(c[1]), "+f"(c[2]), "+f"(c[3])
        : "r"(a[0]), "r"(a[1]), "r"(a[2]), "r"(a[3]), "r"(b0), "r"(b1));
}
__device__ __forceinline__ void mma16f_init(float* c, const uint32_t* a,
                                            uint32_t b0, uint32_t b1) {
    asm volatile(
        "mma.sync.aligned.m16n8k16.row.col.f32.f16.f16.f32 "
        "{%0,%1,%2,%3}, {%4,%5,%6,%7}, {%8,%9}, {%10,%10,%10,%10};"
        : "=f"(c[0]), "=f"(c[1]), "=f"(c[2]), "=f"(c[3])
        : "r"(a[0]), "r"(a[1]), "r"(a[2]), "r"(a[3]), "r"(b0), "r"(b1),
          "f"(0.0f));
}

__device__ __forceinline__ float rcpf(float v) {
    float r; asm("rcp.approx.f32 %0, %1;" : "=f"(r) : "f"(v)); return r;
}
__device__ __forceinline__ float ex2f(float v) {
    float r; asm("ex2.approx.f32 %0, %1;" : "=f"(r) : "f"(v)); return r;
}
__device__ __forceinline__ float silu_den(float a, float b) {
    return (1.0f + __expf(-a)) * (1.0f + __expf(-b));
}
__device__ __forceinline__ float softplus1(float v) {
    return fmaxf(v, 0.0f) + __logf(1.0f + __expf(-fabsf(v)));
}

// ---------------- prep: fold weights on device ----------------
__global__ void prep_kernel(const float* __restrict__ f_out_w,
                            const float* __restrict__ f_out_b,
                            const float* __restrict__ in_proj_w,
                            const float* __restrict__ conv_w,
                            const float* __restrict__ conv_b,
                            const float* __restrict__ dt_bias,
                            const float* __restrict__ D_skip,
                            const float* __restrict__ norm_w,
                            const float* __restrict__ out_proj_w)
{
    int t = blockIdx.x * blockDim.x + threadIdx.x;
    int stride = gridDim.x * blockDim.x;
    // W1 rows: 0..63 z | 64..127 x | 128..135 B | 136..143 C | 144..151 dt
    for (int i = t; i < 152 * 36; i += stride) {
        int j = i / 36, k = i % 36;
        float s = 0.0f;
        #pragma unroll
        for (int m = 0; m < 32; m++) s += in_proj_w[j * 32 + m] * f_out_w[m * 36 + k];
        float scale = (j >= 64 && j < 144) ? conv_w[(j - 64) * 2 + 1] : 1.0f;
        g_params[P_W1 + i] = s * scale;
    }
    for (int i = t; i < 64 * 32; i += stride) {
        int d = i / 32, o = i % 32;
        g_params[P_WOUT + i] = out_proj_w[o * 64 + d] * norm_w[d];
    }
    for (int i = t; i < 152; i += stride) {
        float s = 0.0f;
        #pragma unroll
        for (int m = 0; m < 32; m++) s += in_proj_w[i * 32 + m] * f_out_b[m];
        float b;
        if (i < 64)       b = s;
        else if (i < 144) b = s * conv_w[(i - 64) * 2 + 1] + conv_b[i - 64];
        else              b = s + dt_bias[i - 144];
        g_params[P_B1 + i] = b;
    }
    for (int i = t; i < 8; i += stride) g_params[P_DSK + i] = D_skip[i];
}

// ---------------- main kernel: warp-MMA, register-resident ----------------
__global__ __launch_bounds__(256, 3)
void mamba_hmma_kernel(const float* __restrict__ x,
                       float* __restrict__ out, int N)
{
    __shared__ uint4    s_frag1q[NREC1Q * 32];  // 19 KB  (fp16 W1, paired chunks)
    __shared__ uint2    s_frag1t[NREC1T * 32];  // 4.75 KB (fp16 W1 tail + bias)
    __shared__ uint2    s_frag2 [NREC2  * 32];  // 4 KB   (fp16 W2, shared yh/yl)
    __shared__ float    s_dsk[8];
    __shared__ float    s_coef[8][16][8];       // [warp][row][head]

    const int tid  = threadIdx.x;
    const int lane = tid & 31;
    const int q    = lane & 3;
    const int g    = lane >> 2;
    const int w    = tid >> 5;

    // ---- build GEMM1 fp16 tables ----
    for (int idx = tid; idx < (NREC1Q + NREC1T) * 32; idx += 256) {
        int rec = idx >> 5, ln = idx & 31;
        int lq = ln & 3, lg = ln >> 2;
        int nt, c0;                                 // first chunk covered
        bool isq = rec < NREC1Q;
        if (isq) { nt = rec >> 1; c0 = (rec & 1) * 2; }
        else     { nt = rec - NREC1Q; c0 = 4; }
        int ch = nt * 8 + lg;
        const float* wr = g_params + P_W1 + ch * 36;
        float b = g_params[P_B1 + ch];
        float bhf = __half2float(__float2half_rn(b));
        auto T = [&](int i) -> float {
            if (i < 36)  return __half2float(__float2half_rn(wr[i]));
            if (i < 40)  return 0.0f;
            if (i < 76)  return __half2float(__float2half_rn(wr[i - 40]));
            if (i == 76) return bhf;
            if (i == 77) return b - bhf;
            return 0.0f;
        };
        int ka = 16 * c0 + 2 * lq;
        uint32_t r0 = pkh2(T(ka),      T(ka + 1));
        uint32_t r1 = pkh2(T(ka + 8),  T(ka + 9));
        if (isq) {
            int kb = 16 * (c0 + 1) + 2 * lq;
            uint32_t r2 = pkh2(T(kb),     T(kb + 1));
            uint32_t r3 = pkh2(T(kb + 8), T(kb + 9));
            s_frag1q[idx] = make_uint4(r0, r1, r2, r3);
        } else {
            s_frag1t[(rec - NREC1Q) * 32 + ln] = make_uint2(r0, r1);
        }
    }
    // ---- build GEMM2 fp16 table (single term, shared by yh and yl) ----
    for (int idx = tid; idx < NREC2 * 32; idx += 256) {
        int rec = idx >> 5, ln = idx & 31;
        int lq = ln & 3, lg = ln >> 2;
        int nt = rec >> 2, t = rec & 3;
        int o = nt * 8 + lg;
        int k0 = t * 16 + 2 * lq;
        const float* w2 = g_params + P_WOUT;
        s_frag2[idx] = make_uint2(
            pkh2(w2[(k0    ) * 32 + o], w2[(k0 + 1) * 32 + o]),
            pkh2(w2[(k0 + 8) * 32 + o], w2[(k0 + 9) * 32 + o]));
    }
    if (tid < 8) s_dsk[tid] = g_params[P_DSK + tid];
    __syncthreads();

    const int warp_global = blockIdx.x * 8 + w;
    const int nwarps = gridDim.x * 8;
    const int nchunks = (N + 15) >> 4;
    const uint32_t onesH = pkh2(1.0f, 1.0f);

    for (int chk = warp_global; chk < nchunks; chk += nwarps) {
        const int r0 = (chk << 4) + g;
        const int r1 = r0 + 8;
        const bool p0 = r0 < N, p1 = r1 < N;
        const float* rp0 = x + (size_t)r0 * IN_DIM;
        const float* rp1 = x + (size_t)r1 * IN_DIM;

        // ---- load x pairs and build fp16 two-level split ----
        uint32_t XH[2][5], XL[2][5];
        #pragma unroll
        for (int i = 0; i < 4; i++) {
            int c = i * 8 + 2 * q;
            float2 v0 = p0 ? *(const float2*)(rp0 + c) : make_float2(0.f, 0.f);
            float2 v1 = p1 ? *(const float2*)(rp1 + c) : make_float2(0.f, 0.f);
            uint32_t h0 = pkh2(v0.x, v0.y), h1 = pkh2(v1.x, v1.y);
            float2 f0 = h2f2(h0), f1 = h2f2(h1);
            XH[0][i] = h0; XL[0][i] = pkh2(v0.x - f0.x, v0.y - f0.y);
            XH[1][i] = h1; XL[1][i] = pkh2(v1.x - f1.x, v1.y - f1.y);
        }
        if (q < 2) {
            int c = 32 + 2 * q;
            float2 v0 = p0 ? *(const float2*)(rp0 + c) : make_float2(0.f, 0.f);
            float2 v1 = p1 ? *(const float2*)(rp1 + c) : make_float2(0.f, 0.f);
            uint32_t h0 = pkh2(v0.x, v0.y), h1 = pkh2(v1.x, v1.y);
            float2 f0 = h2f2(h0), f1 = h2f2(h1);
            XH[0][4] = h0; XL[0][4] = pkh2(v0.x - f0.x, v0.y - f0.y);
            XH[1][4] = h1; XL[1][4] = pkh2(v1.x - f1.x, v1.y - f1.y);
        } else {
            XH[0][4] = 0u; XL[0][4] = (q == 2) ? onesH : 0u;
            XH[1][4] = 0u; XL[1][4] = (q == 2) ? onesH : 0u;
        }

        uint32_t A0[4] = { XH[0][0], XH[1][0], XH[0][1], XH[1][1] };
        uint32_t A1[4] = { XH[0][2], XH[1][2], XH[0][3], XH[1][3] };
        uint32_t A2[4] = { XH[0][4], XH[1][4], XL[0][0], XL[1][0] };
        uint32_t A3[4] = { XL[0][1], XL[1][1], XL[0][2], XL[1][2] };
        uint32_t A4[4] = { XL[0][3], XL[1][3], XL[0][4], XL[1][4] };

        // GEMM1 for one n-tile: 5 fp16 MMAs, 2 LDS.128 + 1 LDS.64
        #define GEMM1_NT(nt, c) do {                                          \
            uint4 fA = s_frag1q[((nt) * 2 + 0) * 32 + lane];                  \
            mma16f_init(c, A0, fA.x, fA.y);                                   \
            mma16f(c, A1, fA.z, fA.w);                                        \
            uint4 fB = s_frag1q[((nt) * 2 + 1) * 32 + lane];                  \
            mma16f(c, A2, fB.x, fB.y);                                        \
            mma16f(c, A3, fB.z, fB.w);                                        \
            uint2 ft = s_frag1t[(nt) * 32 + lane];                            \
            mma16f(c, A4, ft.x, ft.y);                                        \
        } while (0)

        // ---- B, C, dt n-tiles (16,17,18) ----
        float cB[4], cC[4], cD[4];
        GEMM1_NT(16, cB);
        GEMM1_NT(17, cC);
        GEMM1_NT(18, cD);

        // bc per row: 4 silu-pairs, ONE rcp (batched inverse)
        float pr0, pr1;
        {
            float n0 = cB[0] * cC[0], n1 = cB[1] * cC[1];
            float n2 = cB[2] * cC[2], n3 = cB[3] * cC[3];
            float d0 = silu_den(cB[0], cC[0]);
            float d1 = silu_den(cB[1], cC[1]);
            float d2 = silu_den(cB[2], cC[2]);
            float d3 = silu_den(cB[3], cC[3]);
            float p01 = d0 * d1, p23 = d2 * d3;
            float r = rcpf(p01 * p23);
            float r01 = r * p23, r23 = r * p01;
            pr0 = n0 * (d1 * r01) + n1 * (d0 * r01);
            pr1 = n2 * (d3 * r23) + n3 * (d2 * r23);
        }
        pr0 += __shfl_xor_sync(0xffffffffu, pr0, 1);
        pr0 += __shfl_xor_sync(0xffffffffu, pr0, 2);
        pr1 += __shfl_xor_sync(0xffffffffu, pr1, 1);
        pr1 += __shfl_xor_sync(0xffffffffu, pr1, 2);

        // coef[head] = softplus(dt)*bc + D_skip  -> shared scratch (per warp)
        {
            float dsk0 = s_dsk[2 * q], dsk1 = s_dsk[2 * q + 1];
            float k00 = softplus1(cD[0]) * pr0 + dsk0;
            float k01 = softplus1(cD[1]) * pr0 + dsk1;
            float k10 = softplus1(cD[2]) * pr1 + dsk0;
            float k11 = softplus1(cD[3]) * pr1 + dsk1;
            __syncwarp();
            *(float2*)&s_coef[w][g][2 * q]     = make_float2(k00, k01);
            *(float2*)&s_coef[w][g + 8][2 * q] = make_float2(k10, k11);
            __syncwarp();
        }

        // ---- z/x n-tiles -> gated y -> fp16 GEMM2 (yh+yl exact, single W term) ----
        float co[16];
        float ss0 = 0.0f, ss1 = 0.0f;

        #pragma unroll
        for (int t = 0; t < 4; t++) {
            uint32_t a2h[4], a2l[4];
            #pragma unroll
            for (int u = 0; u < 2; u++) {
                const int j = 2 * t + u;
                float cz[4], cx[4];
                GEMM1_NT(j, cz);
                GEMM1_NT(8 + j, cx);
                float cf0 = s_coef[w][g][j];
                float cf1 = s_coef[w][g + 8][j];
                // 4 silu-pairs, ONE rcp
                float n0 = cx[0] * cz[0] * cf0, n1 = cx[1] * cz[1] * cf0;
                float n2 = cx[2] * cz[2] * cf1, n3 = cx[3] * cz[3] * cf1;
                float d0 = silu_den(cx[0], cz[0]);
                float d1 = silu_den(cx[1], cz[1]);
                float d2 = silu_den(cx[2], cz[2]);
                float d3 = silu_den(cx[3], cz[3]);
                float p01 = d0 * d1, p23 = d2 * d3;
                float r = rcpf(p01 * p23);
                float r01 = r * p23, r23 = r * p01;
                float y00 = n0 * (d1 * r01);
                float y01 = n1 * (d0 * r01);
                float y10 = n2 * (d3 * r23);
                float y11 = n3 * (d2 * r23);
                ss0 += y00 * y00 + y01 * y01;
                ss1 += y10 * y10 + y11 * y11;
                uint32_t h0 = pkh2(y00, y01), h1 = pkh2(y10, y11);
                float2 f0 = h2f2(h0), f1 = h2f2(h1);
                a2h[2*u]     = h0;
                a2h[2*u + 1] = h1;
                a2l[2*u]     = pkh2(y00 - f0.x, y01 - f0.y);
                a2l[2*u + 1] = pkh2(y10 - f1.x, y11 - f1.y);
            }
            #pragma unroll
            for (int nt = 0; nt < 4; nt++) {
                uint2 f = s_frag2[(nt * 4 + t) * 32 + lane];
                if (t == 0) mma16f_init(co + nt * 4, a2h, f.x, f.y);
                else        mma16f(co + nt * 4, a2h, f.x, f.y);
                mma16f(co + nt * 4, a2l, f.x, f.y);
            }
        }
        #undef GEMM1_NT

        ss0 += __shfl_xor_sync(0xffffffffu, ss0, 1);
        ss0 += __shfl_xor_sync(0xffffffffu, ss0, 2);
        ss1 += __shfl_xor_sync(0xffffffffu, ss1, 1);
        ss1 += __shfl_xor_sync(0xffffffffu, ss1, 2);
        // fold log2(e) into the RMS scale: softmax done in ex2 domain
        float sc0 = rsqrtf(ss0 * (1.0f / 64.0f) + NORM_EPS) * L2E;
        float sc1 = rsqrtf(ss1 * (1.0f / 64.0f) + NORM_EPS) * L2E;

        // ---- softmax over 32, max-free (|logit| bounded -> ex2 args safe) ----
        float lg0[8], lg1[8];
        float s0 = 0.f, s1 = 0.f;
        #pragma unroll
        for (int nt = 0; nt < 4; nt++) {
            lg0[nt * 2]     = ex2f(co[nt * 4 + 0] * sc0);
            lg0[nt * 2 + 1] = ex2f(co[nt * 4 + 1] * sc0);
            lg1[nt * 2]     = ex2f(co[nt * 4 + 2] * sc1);
            lg1[nt * 2 + 1] = ex2f(co[nt * 4 + 3] * sc1);
        }
        #pragma unroll
        for (int i = 0; i < 8; i++) { s0 += lg0[i]; s1 += lg1[i]; }
        s0 += __shfl_xor_sync(0xffffffffu, s0, 1);
        s0 += __shfl_xor_sync(0xffffffffu, s0, 2);
        s1 += __shfl_xor_sync(0xffffffffu, s1, 1);
        s1 += __shfl_xor_sync(0xffffffffu, s1, 2);
        float i0 = rcpf(s0), i1 = rcpf(s1);

        if (p0) {
            float* o0 = out + (size_t)r0 * 32 + 2 * q;
            #pragma unroll
            for (int nt = 0; nt < 4; nt++)
                *(float2*)(o0 + nt * 8) = make_float2(lg0[nt*2] * i0, lg0[nt*2+1] * i0);
        }
        if (p1) {
            float* o1 = out + (size_t)r1 * 32 + 2 * q;
            #pragma unroll
            for (int nt = 0; nt < 4; nt++)
                *(float2*)(o1 + nt * 8) = make_float2(lg1[nt*2] * i1, lg1[nt*2+1] * i1);
        }
    }
}

// ---------------- launch ----------------
extern "C" void kernel_launch(void* const* d_in, const int* in_sizes, int n_in,
                              void* d_out, int out_size)
{
    const float* x         = (const float*)d_in[0];
    const float* f_out_w   = (const float*)d_in[1];
    const float* f_out_b   = (const float*)d_in[2];
    const float* in_proj_w = (const float*)d_in[3];
    const float* conv_w    = (const float*)d_in[4];
    const float* conv_b    = (const float*)d_in[5];
    const float* dt_bias   = (const float*)d_in[6];
    // d_in[7] = A_log (unused by the reference math)
    const float* D_skip    = (const float*)d_in[8];
    const float* norm_w    = (const float*)d_in[9];
    const float* out_proj_w= (const float*)d_in[10];

    int N = in_sizes[0] / IN_DIM;

    prep_kernel<<<48, 128>>>(f_out_w, f_out_b, in_proj_w, conv_w, conv_b,
                             dt_bias, D_skip, norm_w, out_proj_w);

    mamba_hmma_kernel<<<444, 256>>>(x, (float*)d_out, N);
}

// round 16
// speedup vs baseline: 1.3676x; 1.1224x over previous
#include <cuda_runtime.h>
#include <cuda_bf16.h>
#include <cuda_fp16.h>
#include <math.h>
#include <stdint.h>

// ---------------- problem constants ----------------
#define IN_DIM   36
#define NORM_EPS 1e-5f
#define L2E      1.4426950408889634f

// folded fp32 params from prep_kernel
#define P_W1   0        // 152*36 : (in_proj @ f_out_w), conv scale folded into rows 64..143
#define P_WOUT 5472     // 64*32  : [d][o] = out_proj[o][d]*norm_w[d]
#define P_B1   7520     // 152    : fully folded biases
#define P_DSK  7840     // 8
#define P_TOTAL 7848

__device__ float g_params[P_TOTAL];

// GEMM1 fp16 tables (K=80 concat: [Wh(36) | 0(4) | Wh(36) | bh bl | 0 0]):
//   s_frag1q:  uint4 rec = nt*2 + p  (chunks c=2p, 2p+1)          -> 38 recs
//   s_frag1tp: uint4 rec = j         (tail of tile j | tile 8+j)  -> 8 recs
//   s_frag1ta: uint2 rec = i         (tail of tile 16+i)          -> 3 recs
#define NREC1Q 38
#define NREC1TP 8
#define NREC1TA 3
// GEMM2 fp16 table: uint2 rec = nt*4 + t (nt<4, t<4) -> 16 recs
#define NREC2  16

// ---------------- helpers ----------------
__device__ __forceinline__ uint32_t pkh2(float a, float b) {  // f16x2, lo=a hi=b
    uint32_t r;
    asm("cvt.rn.f16x2.f32 %0, %1, %2;" : "=r"(r) : "f"(b), "f"(a));
    return r;
}
__device__ __forceinline__ float2 h2f2(uint32_t p) {          // unpack f16x2 -> 2 floats
    float lo, hi;
    asm("{.reg .b16 l, h;\n"
        " mov.b32 {l, h}, %2;\n"
        " cvt.f32.f16 %0, l;\n"
        " cvt.f32.f16 %1, h;}"
        : "=f"(lo), "=f"(hi) : "r"(p));
    return make_float2(lo, hi);
}

// fp16 mma
__device__ __forceinline__ void mma16f(float* c, const uint32_t* a,
                                       uint32_t b0, uint32_t b1) {
    asm volatile(
        "mma.sync.aligned.m16n8k16.row.col.f32.f16.f16.f32 "
        "{%0,%1,%2,%3}, {%4,%5,%6,%7}, {%8,%9}, {%0,%1,%2,%3};"
        : "+f"(c[0]), "+f"(c[1]), "+f"(c[2]), "+f"(c[3])
        : "r"(a[0]), "r"(a[1]), "r"(a[2]), "r"(a[3]), "r"(b0), "r"(b1));
}
__device__ __forceinline__ void mma16f_init(float* c, const uint32_t* a,
                                            uint32_t b0, uint32_t b1) {
    asm volatile(
        "mma.sync.aligned.m16n8k16.row.col.f32.f16.f16.f32 "
        "{%0,%1,%2,%3}, {%4,%5,%6,%7}, {%8,%9}, {%10,%10,%10,%10};"
        : "=f"(c[0]), "=f"(c[1]), "=f"(c[2]), "=f"(c[3])
        : "r"(a[0]), "r"(a[1]), "r"(a[2]), "r"(a[3]), "r"(b0), "r"(b1),
          "f"(0.0f));
}

__device__ __forceinline__ float rcpf(float v) {
    float r; asm("rcp.approx.f32 %0, %1;" : "=f"(r) : "f"(v)); return r;
}
__device__ __forceinline__ float ex2f(float v) {
    float r; asm("ex2.approx.f32 %0, %1;" : "=f"(r) : "f"(v)); return r;
}
__device__ __forceinline__ float silu_den(float a, float b) {
    return (1.0f + __expf(-a)) * (1.0f + __expf(-b));
}
__device__ __forceinline__ float softplus1(float v) {
    return fmaxf(v, 0.0f) + __logf(1.0f + __expf(-fabsf(v)));
}

// ---------------- prep: fold weights on device ----------------
__global__ void prep_kernel(const float* __restrict__ f_out_w,
                            const float* __restrict__ f_out_b,
                            const float* __restrict__ in_proj_w,
                            const float* __restrict__ conv_w,
                            const float* __restrict__ conv_b,
                            const float* __restrict__ dt_bias,
                            const float* __restrict__ D_skip,
                            const float* __restrict__ norm_w,
                            const float* __restrict__ out_proj_w)
{
    int t = blockIdx.x * blockDim.x + threadIdx.x;
    int stride = gridDim.x * blockDim.x;
    // W1 rows: 0..63 z | 64..127 x | 128..135 B | 136..143 C | 144..151 dt
    for (int i = t; i < 152 * 36; i += stride) {
        int j = i / 36, k = i % 36;
        float s = 0.0f;
        #pragma unroll
        for (int m = 0; m < 32; m++) s += in_proj_w[j * 32 + m] * f_out_w[m * 36 + k];
        float scale = (j >= 64 && j < 144) ? conv_w[(j - 64) * 2 + 1] : 1.0f;
        g_params[P_W1 + i] = s * scale;
    }
    for (int i = t; i < 64 * 32; i += stride) {
        int d = i / 32, o = i % 32;
        g_params[P_WOUT + i] = out_proj_w[o * 64 + d] * norm_w[d];
    }
    for (int i = t; i < 152; i += stride) {
        float s = 0.0f;
        #pragma unroll
        for (int m = 0; m < 32; m++) s += in_proj_w[i * 32 + m] * f_out_b[m];
        float b;
        if (i < 64)       b = s;
        else if (i < 144) b = s * conv_w[(i - 64) * 2 + 1] + conv_b[i - 64];
        else              b = s + dt_bias[i - 144];
        g_params[P_B1 + i] = b;
    }
    for (int i = t; i < 8; i += stride) g_params[P_DSK + i] = D_skip[i];
}

// ---------------- main kernel: warp-MMA, register-resident ----------------
__global__ __launch_bounds__(256, 3)
void mamba_hmma_kernel(const float* __restrict__ x,
                       float* __restrict__ out, int N)
{
    __shared__ uint4    s_frag1q [NREC1Q  * 32]; // 19 KB   (fp16 W1, paired chunks)
    __shared__ uint4    s_frag1tp[NREC1TP * 32]; // 4 KB    (tails, tile j | 8+j)
    __shared__ uint2    s_frag1ta[NREC1TA * 32]; // 0.75 KB (tails, tiles 16..18)
    __shared__ uint2    s_frag2  [NREC2   * 32]; // 4 KB    (fp16 W2, single term)
    __shared__ float    s_dsk[8];
    __shared__ float    s_coef[8][16][8];        // [warp][row][head]

    const int tid  = threadIdx.x;
    const int lane = tid & 31;
    const int q    = lane & 3;
    const int g    = lane >> 2;
    const int w    = tid >> 5;

    // ---- build GEMM1 fp16 tables ----
    // tail fragment of one n-tile (k = 64..79 of the concat), per lane
    auto tail_rec = [&](int nt, int lq, int lg, uint32_t& r0, uint32_t& r1) {
        int ch = nt * 8 + lg;
        const float* wr = g_params + P_W1 + ch * 36;
        float b = g_params[P_B1 + ch];
        float bhf = __half2float(__float2half_rn(b));
        auto T = [&](int i) -> float {
            if (i < 76)  return __half2float(__float2half_rn(wr[i - 40]));
            if (i == 76) return bhf;
            if (i == 77) return b - bhf;
            return 0.0f;
        };
        int ka = 64 + 2 * lq;
        r0 = pkh2(T(ka),     T(ka + 1));
        r1 = pkh2(T(ka + 8), T(ka + 9));
    };
    for (int idx = tid; idx < NREC1Q * 32; idx += 256) {
        int rec = idx >> 5, ln = idx & 31;
        int lq = ln & 3, lg = ln >> 2;
        int nt = rec >> 1, c0 = (rec & 1) * 2;
        int ch = nt * 8 + lg;
        const float* wr = g_params + P_W1 + ch * 36;
        auto T = [&](int i) -> float {
            if (i < 36)  return __half2float(__float2half_rn(wr[i]));
            if (i < 40)  return 0.0f;
            if (i < 76)  return __half2float(__float2half_rn(wr[i - 40]));
            return 0.0f;
        };
        int ka = 16 * c0 + 2 * lq;
        int kb = 16 * (c0 + 1) + 2 * lq;
        s_frag1q[idx] = make_uint4(pkh2(T(ka),     T(ka + 1)),
                                   pkh2(T(ka + 8), T(ka + 9)),
                                   pkh2(T(kb),     T(kb + 1)),
                                   pkh2(T(kb + 8), T(kb + 9)));
    }
    for (int idx = tid; idx < NREC1TP * 32; idx += 256) {
        int j = idx >> 5, ln = idx & 31;
        int lq = ln & 3, lg = ln >> 2;
        uint32_t a0, a1, b0, b1;
        tail_rec(j,     lq, lg, a0, a1);
        tail_rec(8 + j, lq, lg, b0, b1);
        s_frag1tp[idx] = make_uint4(a0, a1, b0, b1);
    }
    for (int idx = tid; idx < NREC1TA * 32; idx += 256) {
        int i = idx >> 5, ln = idx & 31;
        int lq = ln & 3, lg = ln >> 2;
        uint32_t r0, r1;
        tail_rec(16 + i, lq, lg, r0, r1);
        s_frag1ta[idx] = make_uint2(r0, r1);
    }
    // ---- build GEMM2 fp16 table (single term) ----
    for (int idx = tid; idx < NREC2 * 32; idx += 256) {
        int rec = idx >> 5, ln = idx & 31;
        int lq = ln & 3, lg = ln >> 2;
        int nt = rec >> 2, t = rec & 3;
        int o = nt * 8 + lg;
        int k0 = t * 16 + 2 * lq;
        const float* w2 = g_params + P_WOUT;
        s_frag2[idx] = make_uint2(
            pkh2(w2[(k0    ) * 32 + o], w2[(k0 + 1) * 32 + o]),
            pkh2(w2[(k0 + 8) * 32 + o], w2[(k0 + 9) * 32 + o]));
    }
    if (tid < 8) s_dsk[tid] = g_params[P_DSK + tid];
    __syncthreads();

    const int warp_global = blockIdx.x * 8 + w;
    const int nwarps = gridDim.x * 8;
    const int nchunks = (N + 15) >> 4;
    const uint32_t onesH = pkh2(1.0f, 1.0f);

    for (int chk = warp_global; chk < nchunks; chk += nwarps) {
        const int r0 = (chk << 4) + g;
        const int r1 = r0 + 8;
        const bool p0 = r0 < N, p1 = r1 < N;
        const float* rp0 = x + (size_t)r0 * IN_DIM;
        const float* rp1 = x + (size_t)r1 * IN_DIM;

        // ---- load x pairs and build fp16 two-level split ----
        uint32_t XH[2][5], XL[2][5];
        #pragma unroll
        for (int i = 0; i < 4; i++) {
            int c = i * 8 + 2 * q;
            float2 v0 = p0 ? *(const float2*)(rp0 + c) : make_float2(0.f, 0.f);
            float2 v1 = p1 ? *(const float2*)(rp1 + c) : make_float2(0.f, 0.f);
            uint32_t h0 = pkh2(v0.x, v0.y), h1 = pkh2(v1.x, v1.y);
            float2 f0 = h2f2(h0), f1 = h2f2(h1);
            XH[0][i] = h0; XL[0][i] = pkh2(v0.x - f0.x, v0.y - f0.y);
            XH[1][i] = h1; XL[1][i] = pkh2(v1.x - f1.x, v1.y - f1.y);
        }
        if (q < 2) {
            int c = 32 + 2 * q;
            float2 v0 = p0 ? *(const float2*)(rp0 + c) : make_float2(0.f, 0.f);
            float2 v1 = p1 ? *(const float2*)(rp1 + c) : make_float2(0.f, 0.f);
            uint32_t h0 = pkh2(v0.x, v0.y), h1 = pkh2(v1.x, v1.y);
            float2 f0 = h2f2(h0), f1 = h2f2(h1);
            XH[0][4] = h0; XL[0][4] = pkh2(v0.x - f0.x, v0.y - f0.y);
            XH[1][4] = h1; XL[1][4] = pkh2(v1.x - f1.x, v1.y - f1.y);
        } else {
            XH[0][4] = 0u; XL[0][4] = (q == 2) ? onesH : 0u;
            XH[1][4] = 0u; XL[1][4] = (q == 2) ? onesH : 0u;
        }

        uint32_t A0[4] = { XH[0][0], XH[1][0], XH[0][1], XH[1][1] };
        uint32_t A1[4] = { XH[0][2], XH[1][2], XH[0][3], XH[1][3] };
        uint32_t A2[4] = { XH[0][4], XH[1][4], XL[0][0], XL[1][0] };
        uint32_t A3[4] = { XL[0][1], XL[1][1], XL[0][2], XL[1][2] };
        uint32_t A4[4] = { XL[0][3], XL[1][3], XL[0][4], XL[1][4] };

        // GEMM1 core (4 MMAs from paired chunks); tail supplied at call site
        #define GEMM1_CORE(nt, c) do {                                        \
            uint4 fA = s_frag1q[((nt) * 2 + 0) * 32 + lane];                  \
            mma16f_init(c, A0, fA.x, fA.y);                                   \
            mma16f(c, A1, fA.z, fA.w);                                        \
            uint4 fB = s_frag1q[((nt) * 2 + 1) * 32 + lane];                  \
            mma16f(c, A2, fB.x, fB.y);                                        \
            mma16f(c, A3, fB.z, fB.w);                                        \
        } while (0)

        // ---- B, C, dt n-tiles (16,17,18) ----
        float cB[4], cC[4], cD[4];
        {
            GEMM1_CORE(16, cB);
            uint2 tB = s_frag1ta[0 * 32 + lane];
            mma16f(cB, A4, tB.x, tB.y);
            GEMM1_CORE(17, cC);
            uint2 tC = s_frag1ta[1 * 32 + lane];
            mma16f(cC, A4, tC.x, tC.y);
            GEMM1_CORE(18, cD);
            uint2 tD = s_frag1ta[2 * 32 + lane];
            mma16f(cD, A4, tD.x, tD.y);
        }

        // bc per row: 4 silu-pairs, ONE rcp (batched inverse)
        float pr0, pr1;
        {
            float n0 = cB[0] * cC[0], n1 = cB[1] * cC[1];
            float n2 = cB[2] * cC[2], n3 = cB[3] * cC[3];
            float d0 = silu_den(cB[0], cC[0]);
            float d1 = silu_den(cB[1], cC[1]);
            float d2 = silu_den(cB[2], cC[2]);
            float d3 = silu_den(cB[3], cC[3]);
            float p01 = d0 * d1, p23 = d2 * d3;
            float r = rcpf(p01 * p23);
            float r01 = r * p23, r23 = r * p01;
            pr0 = n0 * (d1 * r01) + n1 * (d0 * r01);
            pr1 = n2 * (d3 * r23) + n3 * (d2 * r23);
        }
        pr0 += __shfl_xor_sync(0xffffffffu, pr0, 1);
        pr0 += __shfl_xor_sync(0xffffffffu, pr0, 2);
        pr1 += __shfl_xor_sync(0xffffffffu, pr1, 1);
        pr1 += __shfl_xor_sync(0xffffffffu, pr1, 2);

        // coef[head] = softplus(dt)*bc + D_skip  -> shared scratch (per warp)
        {
            float dsk0 = s_dsk[2 * q], dsk1 = s_dsk[2 * q + 1];
            float k00 = softplus1(cD[0]) * pr0 + dsk0;
            float k01 = softplus1(cD[1]) * pr0 + dsk1;
            float k10 = softplus1(cD[2]) * pr1 + dsk0;
            float k11 = softplus1(cD[3]) * pr1 + dsk1;
            __syncwarp();
            *(float2*)&s_coef[w][g][2 * q]     = make_float2(k00, k01);
            *(float2*)&s_coef[w][g + 8][2 * q] = make_float2(k10, k11);
            __syncwarp();
        }

        // ---- z/x n-tiles -> gated y (single fp16) -> GEMM2 ----
        float co[16];
        float ss0 = 0.0f, ss1 = 0.0f;

        #pragma unroll
        for (int t = 0; t < 4; t++) {
            uint32_t a2[4];
            #pragma unroll
            for (int u = 0; u < 2; u++) {
                const int j = 2 * t + u;
                float cz[4], cx[4];
                GEMM1_CORE(j, cz);
                GEMM1_CORE(8 + j, cx);
                {   // paired tails: tile j (x,y) and tile 8+j (z,w)
                    uint4 tp = s_frag1tp[j * 32 + lane];
                    mma16f(cz, A4, tp.x, tp.y);
                    mma16f(cx, A4, tp.z, tp.w);
                }
                float cf0 = s_coef[w][g][j];
                float cf1 = s_coef[w][g + 8][j];
                // 4 silu-pairs, ONE rcp
                float n0 = cx[0] * cz[0] * cf0, n1 = cx[1] * cz[1] * cf0;
                float n2 = cx[2] * cz[2] * cf1, n3 = cx[3] * cz[3] * cf1;
                float d0 = silu_den(cx[0], cz[0]);
                float d1 = silu_den(cx[1], cz[1]);
                float d2 = silu_den(cx[2], cz[2]);
                float d3 = silu_den(cx[3], cz[3]);
                float p01 = d0 * d1, p23 = d2 * d3;
                float r = rcpf(p01 * p23);
                float r01 = r * p23, r23 = r * p01;
                float y00 = n0 * (d1 * r01);
                float y01 = n1 * (d0 * r01);
                float y10 = n2 * (d3 * r23);
                float y11 = n3 * (d2 * r23);
                ss0 += y00 * y00 + y01 * y01;
                ss1 += y10 * y10 + y11 * y11;
                a2[2*u]     = pkh2(y00, y01);
                a2[2*u + 1] = pkh2(y10, y11);
            }
            #pragma unroll
            for (int nt = 0; nt < 4; nt++) {
                uint2 f = s_frag2[(nt * 4 + t) * 32 + lane];
                if (t == 0) mma16f_init(co + nt * 4, a2, f.x, f.y);
                else        mma16f(co + nt * 4, a2, f.x, f.y);
            }
        }
        #undef GEMM1_CORE

        ss0 += __shfl_xor_sync(0xffffffffu, ss0, 1);
        ss0 += __shfl_xor_sync(0xffffffffu, ss0, 2);
        ss1 += __shfl_xor_sync(0xffffffffu, ss1, 1);
        ss1 += __shfl_xor_sync(0xffffffffu, ss1, 2);
        // fold log2(e) into the RMS scale: softmax done in ex2 domain
        float sc0 = rsqrtf(ss0 * (1.0f / 64.0f) + NORM_EPS) * L2E;
        float sc1 = rsqrtf(ss1 * (1.0f / 64.0f) + NORM_EPS) * L2E;

        // ---- softmax over 32, max-free (|logit| bounded -> ex2 args safe) ----
        float lg0[8], lg1[8];
        float s0 = 0.f, s1 = 0.f;
        #pragma unroll
        for (int nt = 0; nt < 4; nt++) {
            lg0[nt * 2]     = ex2f(co[nt * 4 + 0] * sc0);
            lg0[nt * 2 + 1] = ex2f(co[nt * 4 + 1] * sc0);
            lg1[nt * 2]     = ex2f(co[nt * 4 + 2] * sc1);
            lg1[nt * 2 + 1] = ex2f(co[nt * 4 + 3] * sc1);
        }
        #pragma unroll
        for (int i = 0; i < 8; i++) { s0 += lg0[i]; s1 += lg1[i]; }
        s0 += __shfl_xor_sync(0xffffffffu, s0, 1);
        s0 += __shfl_xor_sync(0xffffffffu, s0, 2);
        s1 += __shfl_xor_sync(0xffffffffu, s1, 1);
        s1 += __shfl_xor_sync(0xffffffffu, s1, 2);
        float i0 = rcpf(s0), i1 = rcpf(s1);

        if (p0) {
            float* o0 = out + (size_t)r0 * 32 + 2 * q;
            #pragma unroll
            for (int nt = 0; nt < 4; nt++)
                *(float2*)(o0 + nt * 8) = make_float2(lg0[nt*2] * i0, lg0[nt*2+1] * i0);
        }
        if (p1) {
            float* o1 = out + (size_t)r1 * 32 + 2 * q;
            #pragma unroll
            for (int nt = 0; nt < 4; nt++)
                *(float2*)(o1 + nt * 8) = make_float2(lg1[nt*2] * i1, lg1[nt*2+1] * i1);
        }
    }
}

// ---------------- launch ----------------
extern "C" void kernel_launch(void* const* d_in, const int* in_sizes, int n_in,
                              void* d_out, int out_size)
{
    const float* x         = (const float*)d_in[0];
    const float* f_out_w   = (const float*)d_in[1];
    const float* f_out_b   = (const float*)d_in[2];
    const float* in_proj_w = (const float*)d_in[3];
    const float* conv_w    = (const float*)d_in[4];
    const float* conv_b    = (const float*)d_in[5];
    const float* dt_bias   = (const float*)d_in[6];
    // d_in[7] = A_log (unused by the reference math)
    const float* D_skip    = (const float*)d_in[8];
    const float* norm_w    = (const float*)d_in[9];
    const float* out_proj_w= (const float*)d_in[10];

    int N = in_sizes[0] / IN_DIM;

    prep_kernel<<<48, 128>>>(f_out_w, f_out_b, in_proj_w, conv_w, conv_b,
                             dt_bias, D_skip, norm_w, out_proj_w);

    mamba_hmma_kernel<<<444, 256>>>(x, (float*)d_out, N);
}

// round 17
// speedup vs baseline: 1.3681x; 1.0004x over previous
#include <cuda_runtime.h>
#include <cuda_bf16.h>
#include <cuda_fp16.h>
#include <math.h>
#include <stdint.h>

// ---------------- problem constants ----------------
#define IN_DIM   36
#define NORM_EPS 1e-5f
#define L2E      1.4426950408889634f

// folded fp32 params from prep_kernel
#define P_W1   0        // 152*36 : (in_proj @ f_out_w), conv scale folded into rows 64..143
#define P_WOUT 5472     // 64*32  : [d][o] = out_proj[o][d]*norm_w[d]
#define P_B1   7520     // 152    : fully folded biases
#define P_DSK  7840     // 8
#define P_TOTAL 7848

__device__ float g_params[P_TOTAL];

// GEMM1 fp16 tables, K=80 concat with PERMUTED slot->column map:
//   lane q owns pairs p=0..3 -> cols 8q+2p, 8q+2p+1 ; p=4 -> cols 32+2q (q<2)
//   xh region = chunks 0,1 + chunk2 first half; xl mirrors in chunk2 2nd half..chunk4
//   bias (bh,bl) at xl-p4 slot of lane q==2 (A supplies ones there)
//   s_frag1q:  uint4 rec = nt*2 + pp  (chunks 2pp, 2pp+1)        -> 38 recs
//   s_frag1tp: uint4 rec = j          (chunk4 of tile j | 8+j)   -> 8 recs
//   s_frag1ta: uint2 rec = i          (chunk4 of tile 16+i)      -> 3 recs
#define NREC1Q 38
#define NREC1TP 8
#define NREC1TA 3
// GEMM2 fp16 table: uint2 rec = nt*4 + t (nt<4, t<4), PERMUTED cols -> 16 recs
#define NREC2  16

// ---------------- helpers ----------------
__device__ __forceinline__ uint32_t pkh2(float a, float b) {  // f16x2, lo=a hi=b
    uint32_t r;
    asm("cvt.rn.f16x2.f32 %0, %1, %2;" : "=r"(r) : "f"(b), "f"(a));
    return r;
}
__device__ __forceinline__ float2 h2f2(uint32_t p) {          // unpack f16x2 -> 2 floats
    float lo, hi;
    asm("{.reg .b16 l, h;\n"
        " mov.b32 {l, h}, %2;\n"
        " cvt.f32.f16 %0, l;\n"
        " cvt.f32.f16 %1, h;}"
        : "=f"(lo), "=f"(hi) : "r"(p));
    return make_float2(lo, hi);
}

// fp16 mma
__device__ __forceinline__ void mma16f(float* c, const uint32_t* a,
                                       uint32_t b0, uint32_t b1) {
    asm volatile(
        "mma.sync.aligned.m16n8k16.row.col.f32.f16.f16.f32 "
        "{%0,%1,%2,%3}, {%4,%5,%6,%7}, {%8,%9}, {%0,%1,%2,%3};"
        : "+f"(c[0]), "+f"(c[1]), "+f"(c[2]), "+f"(c[3])
        : "r"(a[0]), "r"(a[1]), "r"(a[2]), "r"(a[3]), "r"(b0), "r"(b1));
}
__device__ __forceinline__ void mma16f_init(float* c, const uint32_t* a,
                                            uint32_t b0, uint32_t b1) {
    asm volatile(
        "mma.sync.aligned.m16n8k16.row.col.f32.f16.f16.f32 "
        "{%0,%1,%2,%3}, {%4,%5,%6,%7}, {%8,%9}, {%10,%10,%10,%10};"
        : "=f"(c[0]), "=f"(c[1]), "=f"(c[2]), "=f"(c[3])
        : "r"(a[0]), "r"(a[1]), "r"(a[2]), "r"(a[3]), "r"(b0), "r"(b1),
          "f"(0.0f));
}

__device__ __forceinline__ float rcpf(float v) {
    float r; asm("rcp.approx.f32 %0, %1;" : "=f"(r) : "f"(v)); return r;
}
__device__ __forceinline__ float ex2f(float v) {
    float r; asm("ex2.approx.f32 %0, %1;" : "=f"(r) : "f"(v)); return r;
}
__device__ __forceinline__ float silu_den(float a, float b) {
    return (1.0f + __expf(-a)) * (1.0f + __expf(-b));
}
__device__ __forceinline__ float softplus1(float v) {
    return fmaxf(v, 0.0f) + __logf(1.0f + __expf(-fabsf(v)));
}

// ---------------- prep: fold weights on device ----------------
__global__ void prep_kernel(const float* __restrict__ f_out_w,
                            const float* __restrict__ f_out_b,
                            const float* __restrict__ in_proj_w,
                            const float* __restrict__ conv_w,
                            const float* __restrict__ conv_b,
                            const float* __restrict__ dt_bias,
                            const float* __restrict__ D_skip,
                            const float* __restrict__ norm_w,
                            const float* __restrict__ out_proj_w)
{
    int t = blockIdx.x * blockDim.x + threadIdx.x;
    int stride = gridDim.x * blockDim.x;
    // W1 rows: 0..63 z | 64..127 x | 128..135 B | 136..143 C | 144..151 dt
    for (int i = t; i < 152 * 36; i += stride) {
        int j = i / 36, k = i % 36;
        float s = 0.0f;
        #pragma unroll
        for (int m = 0; m < 32; m++) s += in_proj_w[j * 32 + m] * f_out_w[m * 36 + k];
        float scale = (j >= 64 && j < 144) ? conv_w[(j - 64) * 2 + 1] : 1.0f;
        g_params[P_W1 + i] = s * scale;
    }
    for (int i = t; i < 64 * 32; i += stride) {
        int d = i / 32, o = i % 32;
        g_params[P_WOUT + i] = out_proj_w[o * 64 + d] * norm_w[d];
    }
    for (int i = t; i < 152; i += stride) {
        float s = 0.0f;
        #pragma unroll
        for (int m = 0; m < 32; m++) s += in_proj_w[i * 32 + m] * f_out_b[m];
        float b;
        if (i < 64)       b = s;
        else if (i < 144) b = s * conv_w[(i - 64) * 2 + 1] + conv_b[i - 64];
        else              b = s + dt_bias[i - 144];
        g_params[P_B1 + i] = b;
    }
    for (int i = t; i < 8; i += stride) g_params[P_DSK + i] = D_skip[i];
}

// ---------------- main kernel: warp-MMA, register-resident ----------------
__global__ __launch_bounds__(256, 3)
void mamba_hmma_kernel(const float* __restrict__ x,
                       float* __restrict__ out, int N)
{
    __shared__ uint4    s_frag1q [NREC1Q  * 32]; // 19 KB   (fp16 W1, paired chunks)
    __shared__ uint4    s_frag1tp[NREC1TP * 32]; // 4 KB    (chunk4, tile j | 8+j)
    __shared__ uint2    s_frag1ta[NREC1TA * 32]; // 0.75 KB (chunk4, tiles 16..18)
    __shared__ uint2    s_frag2  [NREC2   * 32]; // 4 KB    (fp16 W2, permuted cols)
    __shared__ float    s_dsk[8];

    const int tid  = threadIdx.x;
    const int lane = tid & 31;
    const int q    = lane & 3;
    const int g    = lane >> 2;
    const int w    = tid >> 5;

    // ---- table value for slot (c, h, e-pair base) of lane lq, tile channel ch ----
    // xh region: chunks 0,1 + chunk2 h0. xl region: chunk2 h1 .. chunk4 h1.
    // pair p<4 -> col 8lq+2p ; p==4 -> (lq<2 ? 32+2lq : bias/zero)
    auto slot_vals = [&](int nt, int c, int h, int lq, float& v0, float& v1) {
        int ch = nt * 8;   // + lg added by caller
        (void)ch;
        bool xh = (c < 2) || (c == 2 && h == 0);
        int p = xh ? (2 * c + h) : (2 * c + h - 5);
        v0 = 0.f; v1 = 0.f;
        // caller fills; placeholder (real logic below)
        (void)p; (void)lq;
    };
    (void)slot_vals;

    // ---- build GEMM1 fp16 tables (permuted slot->col map) ----
    // record component for (nt, c, h, lq, lg): returns packed f16x2
    auto rec_pack = [&](int nt, int c, int h, int lq, int lg) -> uint32_t {
        int ch = nt * 8 + lg;
        const float* wr = g_params + P_W1 + ch * 36;
        bool xh = (c < 2) || (c == 2 && h == 0);
        int p = xh ? (2 * c + h) : (2 * c + h - 5);
        float a, b;
        if (p < 4) {
            int col = 8 * lq + 2 * p;
            float w0 = wr[col], w1 = wr[col + 1];
            if (xh) {
                a = __half2float(__float2half_rn(w0));
                b = __half2float(__float2half_rn(w1));
            } else {
                a = w0 - __half2float(__float2half_rn(w0));
                b = w1 - __half2float(__float2half_rn(w1));
            }
        } else {   // p == 4
            if (lq < 2) {
                int col = 32 + 2 * lq;
                float w0 = wr[col], w1 = wr[col + 1];
                if (xh) {
                    a = __half2float(__float2half_rn(w0));
                    b = __half2float(__float2half_rn(w1));
                } else {
                    a = w0 - __half2float(__float2half_rn(w0));
                    b = w1 - __half2float(__float2half_rn(w1));
                }
            } else if (!xh && lq == 2) {   // bias slot (xl-p4, lane 2)
                float bb = g_params[P_B1 + ch];
                float bh = __half2float(__float2half_rn(bb));
                a = bh; b = bb - bh;
            } else {
                a = 0.f; b = 0.f;
            }
        }
        return pkh2(a, b);
    };

    for (int idx = tid; idx < NREC1Q * 32; idx += 256) {
        int rec = idx >> 5, ln = idx & 31;
        int lq = ln & 3, lg = ln >> 2;
        int nt = rec >> 1, pp = rec & 1;
        s_frag1q[idx] = make_uint4(rec_pack(nt, 2*pp,     0, lq, lg),
                                   rec_pack(nt, 2*pp,     1, lq, lg),
                                   rec_pack(nt, 2*pp + 1, 0, lq, lg),
                                   rec_pack(nt, 2*pp + 1, 1, lq, lg));
    }
    for (int idx = tid; idx < NREC1TP * 32; idx += 256) {
        int j = idx >> 5, ln = idx & 31;
        int lq = ln & 3, lg = ln >> 2;
        s_frag1tp[idx] = make_uint4(rec_pack(j,     4, 0, lq, lg),
                                    rec_pack(j,     4, 1, lq, lg),
                                    rec_pack(8 + j, 4, 0, lq, lg),
                                    rec_pack(8 + j, 4, 1, lq, lg));
    }
    for (int idx = tid; idx < NREC1TA * 32; idx += 256) {
        int i = idx >> 5, ln = idx & 31;
        int lq = ln & 3, lg = ln >> 2;
        s_frag1ta[idx] = make_uint2(rec_pack(16 + i, 4, 0, lq, lg),
                                    rec_pack(16 + i, 4, 1, lq, lg));
    }
    // ---- build GEMM2 fp16 table: permuted cols o = (lg>>1)*8 + (lg&1) + 2*nt ----
    for (int idx = tid; idx < NREC2 * 32; idx += 256) {
        int rec = idx >> 5, ln = idx & 31;
        int lq = ln & 3, lg = ln >> 2;
        int nt = rec >> 2, t = rec & 3;
        int o = ((lg >> 1) << 3) + (lg & 1) + 2 * nt;
        int k0 = t * 16 + 2 * lq;
        const float* w2 = g_params + P_WOUT;
        s_frag2[idx] = make_uint2(
            pkh2(w2[(k0    ) * 32 + o], w2[(k0 + 1) * 32 + o]),
            pkh2(w2[(k0 + 8) * 32 + o], w2[(k0 + 9) * 32 + o]));
    }
    if (tid < 8) s_dsk[tid] = g_params[P_DSK + tid];
    __syncthreads();

    const int warp_global = blockIdx.x * 8 + w;
    const int nwarps = gridDim.x * 8;
    const int nchunks = (N + 15) >> 4;
    const uint32_t onesH = pkh2(1.0f, 1.0f);

    for (int chk = warp_global; chk < nchunks; chk += nwarps) {
        const int r0 = (chk << 4) + g;
        const int r1 = r0 + 8;
        const bool p0 = r0 < N, p1 = r1 < N;
        const float* rp0 = x + (size_t)r0 * IN_DIM;
        const float* rp1 = x + (size_t)r1 * IN_DIM;

        // ---- wide x loads (permuted cols): lane q reads cols 8q..8q+7 (+32+2q q<2) ----
        uint32_t XH[2][5], XL[2][5];
        {
            const int cb = 8 * q;
            float4 F0a = p0 ? *(const float4*)(rp0 + cb)     : make_float4(0,0,0,0);
            float4 F1a = p0 ? *(const float4*)(rp0 + cb + 4) : make_float4(0,0,0,0);
            float4 F0b = p1 ? *(const float4*)(rp1 + cb)     : make_float4(0,0,0,0);
            float4 F1b = p1 ? *(const float4*)(rp1 + cb + 4) : make_float4(0,0,0,0);
            float2 Ea = make_float2(0,0), Eb = make_float2(0,0);
            if (q < 2) {
                if (p0) Ea = *(const float2*)(rp0 + 32 + 2 * q);
                if (p1) Eb = *(const float2*)(rp1 + 32 + 2 * q);
            }
            #define SPLIT(dsth, dstl, a, b) do {                               \
                uint32_t hh = pkh2(a, b);                                      \
                float2 ff = h2f2(hh);                                          \
                dsth = hh;                                                     \
                dstl = pkh2((a) - ff.x, (b) - ff.y);                           \
            } while (0)
            SPLIT(XH[0][0], XL[0][0], F0a.x, F0a.y);
            SPLIT(XH[0][1], XL[0][1], F0a.z, F0a.w);
            SPLIT(XH[0][2], XL[0][2], F1a.x, F1a.y);
            SPLIT(XH[0][3], XL[0][3], F1a.z, F1a.w);
            SPLIT(XH[0][4], XL[0][4], Ea.x,  Ea.y);
            SPLIT(XH[1][0], XL[1][0], F0b.x, F0b.y);
            SPLIT(XH[1][1], XL[1][1], F0b.z, F0b.w);
            SPLIT(XH[1][2], XL[1][2], F1b.x, F1b.y);
            SPLIT(XH[1][3], XL[1][3], F1b.z, F1b.w);
            SPLIT(XH[1][4], XL[1][4], Eb.x,  Eb.y);
            #undef SPLIT
            if (q >= 2) {
                XH[0][4] = 0u; XH[1][4] = 0u;
                XL[0][4] = (q == 2) ? onesH : 0u;
                XL[1][4] = (q == 2) ? onesH : 0u;
            }
        }

        uint32_t A0[4] = { XH[0][0], XH[1][0], XH[0][1], XH[1][1] };
        uint32_t A1[4] = { XH[0][2], XH[1][2], XH[0][3], XH[1][3] };
        uint32_t A2[4] = { XH[0][4], XH[1][4], XL[0][0], XL[1][0] };
        uint32_t A3[4] = { XL[0][1], XL[1][1], XL[0][2], XL[1][2] };
        uint32_t A4[4] = { XL[0][3], XL[1][3], XL[0][4], XL[1][4] };

        // GEMM1 core (4 MMAs from paired chunks); chunk4 supplied at call site
        #define GEMM1_CORE(nt, c) do {                                        \
            uint4 fA = s_frag1q[((nt) * 2 + 0) * 32 + lane];                  \
            mma16f_init(c, A0, fA.x, fA.y);                                   \
            mma16f(c, A1, fA.z, fA.w);                                        \
            uint4 fB = s_frag1q[((nt) * 2 + 1) * 32 + lane];                  \
            mma16f(c, A2, fB.x, fB.y);                                        \
            mma16f(c, A3, fB.z, fB.w);                                        \
        } while (0)

        // ---- B, C, dt n-tiles (16,17,18) ----
        float cB[4], cC[4], cD[4];
        {
            GEMM1_CORE(16, cB);
            uint2 tB = s_frag1ta[0 * 32 + lane];
            mma16f(cB, A4, tB.x, tB.y);
            GEMM1_CORE(17, cC);
            uint2 tC = s_frag1ta[1 * 32 + lane];
            mma16f(cC, A4, tC.x, tC.y);
            GEMM1_CORE(18, cD);
            uint2 tD = s_frag1ta[2 * 32 + lane];
            mma16f(cD, A4, tD.x, tD.y);
        }

        // bc per row: 4 silu-pairs, ONE rcp (batched inverse)
        float pr0, pr1;
        {
            float n0 = cB[0] * cC[0], n1 = cB[1] * cC[1];
            float n2 = cB[2] * cC[2], n3 = cB[3] * cC[3];
            float d0 = silu_den(cB[0], cC[0]);
            float d1 = silu_den(cB[1], cC[1]);
            float d2 = silu_den(cB[2], cC[2]);
            float d3 = silu_den(cB[3], cC[3]);
            float p01 = d0 * d1, p23 = d2 * d3;
            float r = rcpf(p01 * p23);
            float r01 = r * p23, r23 = r * p01;
            pr0 = n0 * (d1 * r01) + n1 * (d0 * r01);
            pr1 = n2 * (d3 * r23) + n3 * (d2 * r23);
        }
        pr0 += __shfl_xor_sync(0xffffffffu, pr0, 1);
        pr0 += __shfl_xor_sync(0xffffffffu, pr0, 2);
        pr1 += __shfl_xor_sync(0xffffffffu, pr1, 1);
        pr1 += __shfl_xor_sync(0xffffffffu, pr1, 2);

        // coef in registers: lane q holds heads 2q, 2q+1 of rows g / g+8
        float k00, k01, k10, k11;
        {
            float dsk0 = s_dsk[2 * q], dsk1 = s_dsk[2 * q + 1];
            k00 = softplus1(cD[0]) * pr0 + dsk0;
            k01 = softplus1(cD[1]) * pr0 + dsk1;
            k10 = softplus1(cD[2]) * pr1 + dsk0;
            k11 = softplus1(cD[3]) * pr1 + dsk1;
        }

        // ---- z/x n-tiles -> gated y (single fp16) -> GEMM2 ----
        float co[16];
        float ss0 = 0.0f, ss1 = 0.0f;

        #pragma unroll
        for (int t = 0; t < 4; t++) {
            uint32_t a2[4];
            #pragma unroll
            for (int u = 0; u < 2; u++) {
                const int j = 2 * t + u;
                float cz[4], cx[4];
                GEMM1_CORE(j, cz);
                GEMM1_CORE(8 + j, cx);
                {   // paired chunk4: tile j (x,y) and tile 8+j (z,w)
                    uint4 tp = s_frag1tp[j * 32 + lane];
                    mma16f(cz, A4, tp.x, tp.y);
                    mma16f(cx, A4, tp.z, tp.w);
                }
                // coef broadcast via shuffle (head j lives at lane (g, j>>1))
                const int src = (lane & ~3) | (j >> 1);
                float cf0 = __shfl_sync(0xffffffffu, (j & 1) ? k01 : k00, src);
                float cf1 = __shfl_sync(0xffffffffu, (j & 1) ? k11 : k10, src);
                // 4 silu-pairs, ONE rcp
                float n0 = cx[0] * cz[0] * cf0, n1 = cx[1] * cz[1] * cf0;
                float n2 = cx[2] * cz[2] * cf1, n3 = cx[3] * cz[3] * cf1;
                float d0 = silu_den(cx[0], cz[0]);
                float d1 = silu_den(cx[1], cz[1]);
                float d2 = silu_den(cx[2], cz[2]);
                float d3 = silu_den(cx[3], cz[3]);
                float p01 = d0 * d1, p23 = d2 * d3;
                float r = rcpf(p01 * p23);
                float r01 = r * p23, r23 = r * p01;
                float y00 = n0 * (d1 * r01);
                float y01 = n1 * (d0 * r01);
                float y10 = n2 * (d3 * r23);
                float y11 = n3 * (d2 * r23);
                ss0 += y00 * y00 + y01 * y01;
                ss1 += y10 * y10 + y11 * y11;
                a2[2*u]     = pkh2(y00, y01);
                a2[2*u + 1] = pkh2(y10, y11);
            }
            #pragma unroll
            for (int nt = 0; nt < 4; nt++) {
                uint2 f = s_frag2[(nt * 4 + t) * 32 + lane];
                if (t == 0) mma16f_init(co + nt * 4, a2, f.x, f.y);
                else        mma16f(co + nt * 4, a2, f.x, f.y);
            }
        }
        #undef GEMM1_CORE

        ss0 += __shfl_xor_sync(0xffffffffu, ss0, 1);
        ss0 += __shfl_xor_sync(0xffffffffu, ss0, 2);
        ss1 += __shfl_xor_sync(0xffffffffu, ss1, 1);
        ss1 += __shfl_xor_sync(0xffffffffu, ss1, 2);
        // fold log2(e) into the RMS scale: softmax done in ex2 domain
        float sc0 = rsqrtf(ss0 * (1.0f / 64.0f) + NORM_EPS) * L2E;
        float sc1 = rsqrtf(ss1 * (1.0f / 64.0f) + NORM_EPS) * L2E;

        // ---- softmax over 32, max-free; lane q owns contiguous cols 8q..8q+7 ----
        // co[nt*4 + e]   = row r0, col 8q + 2*nt + e
        // co[nt*4 + 2+e] = row r1, col 8q + 2*nt + e
        float lg0[8], lg1[8];
        float s0 = 0.f, s1 = 0.f;
        #pragma unroll
        for (int nt = 0; nt < 4; nt++) {
            lg0[2 * nt]     = ex2f(co[nt * 4 + 0] * sc0);
            lg0[2 * nt + 1] = ex2f(co[nt * 4 + 1] * sc0);
            lg1[2 * nt]     = ex2f(co[nt * 4 + 2] * sc1);
            lg1[2 * nt + 1] = ex2f(co[nt * 4 + 3] * sc1);
        }
        #pragma unroll
        for (int i = 0; i < 8; i++) { s0 += lg0[i]; s1 += lg1[i]; }
        s0 += __shfl_xor_sync(0xffffffffu, s0, 1);
        s0 += __shfl_xor_sync(0xffffffffu, s0, 2);
        s1 += __shfl_xor_sync(0xffffffffu, s1, 1);
        s1 += __shfl_xor_sync(0xffffffffu, s1, 2);
        float i0 = rcpf(s0), i1 = rcpf(s1);

        if (p0) {
            float4* o0 = (float4*)(out + (size_t)r0 * 32 + 8 * q);
            o0[0] = make_float4(lg0[0] * i0, lg0[1] * i0, lg0[2] * i0, lg0[3] * i0);
            o0[1] = make_float4(lg0[4] * i0, lg0[5] * i0, lg0[6] * i0, lg0[7] * i0);
        }
        if (p1) {
            float4* o1 = (float4*)(out + (size_t)r1 * 32 + 8 * q);
            o1[0] = make_float4(lg1[0] * i1, lg1[1] * i1, lg1[2] * i1, lg1[3] * i1);
            o1[1] = make_float4(lg1[4] * i1, lg1[5] * i1, lg1[6] * i1, lg1[7] * i1);
        }
    }
}

// ---------------- launch ----------------
extern "C" void kernel_launch(void* const* d_in, const int* in_sizes, int n_in,
                              void* d_out, int out_size)
{
    const float* x         = (const float*)d_in[0];
    const float* f_out_w   = (const float*)d_in[1];
    const float* f_out_b   = (const float*)d_in[2];
    const float* in_proj_w = (const float*)d_in[3];
    const float* conv_w    = (const float*)d_in[4];
    const float* conv_b    = (const float*)d_in[5];
    const float* dt_bias   = (const float*)d_in[6];
    // d_in[7] = A_log (unused by the reference math)
    const float* D_skip    = (const float*)d_in[8];
    const float* norm_w    = (const float*)d_in[9];
    const float* out_proj_w= (const float*)d_in[10];

    int N = in_sizes[0] / IN_DIM;

    prep_kernel<<<48, 128>>>(f_out_w, f_out_b, in_proj_w, conv_w, conv_b,
                             dt_bias, D_skip, norm_w, out_proj_w);

    mamba_hmma_kernel<<<444, 256>>>(x, (float*)d_out, N);
}